// round 5
// baseline (speedup 1.0000x reference)
#include <cuda_runtime.h>

// Problem constants (shapes fixed by setup_inputs)
#define NMAX   50000
#define EAMAX  850000     // E + N self loops
#define F_IN   128
#define HC     256        // heads*out_ch layer 1
#define H1     4
#define CH1    64         // agg1 edge chunk
#define SCB    1024       // scan block size

// gemm tiling
#define BM 128
#define BN 128
#define BK 16
#define ASTRIDE 260

typedef unsigned long long u64;

// ---------------- scratch (static __device__, allocation-free) ----------------
__device__ float    g_h1[NMAX * HC];
__device__ float    g_Wt[F_IN * HC];       // W1 transposed [k][c]
__device__ float    g_as1[NMAX * H1];
__device__ float    g_ad1[NMAX * H1];
__device__ int      g_src[EAMAX];
__device__ int      g_dst[EAMAX];
__device__ int      g_cnt[NMAX];
__device__ int      g_rowstart[NMAX];
__device__ int      g_fill[NMAX];
__device__ int      g_csr_src[EAMAX];
__device__ int      g_bsum[64];            // scan block sums
__device__ int      g_boff[64];            // scanned block offsets
__device__ float    g_h2[NMAX * 2];
__device__ float    g_as2[NMAX];
__device__ float    g_ad2[NMAX];
__device__ int      g_is64;

// ---------------- helpers ----------------
__device__ __forceinline__ float lrelu(float x) { return x > 0.f ? x : 0.2f * x; }

__device__ __forceinline__ u64 pack2(float lo, float hi) {
    u64 r;
    asm("mov.b64 %0, {%1, %2};" : "=l"(r) : "f"(lo), "f"(hi));
    return r;
}
__device__ __forceinline__ void unpack2(u64 v, float& lo, float& hi) {
    asm("mov.b64 {%0, %1}, %2;" : "=f"(lo), "=f"(hi) : "l"(v));
}
__device__ __forceinline__ u64 fma2(u64 a, u64 b, u64 c) {
    u64 d;
    asm("fma.rn.f32x2 %0, %1, %2, %3;" : "=l"(d) : "l"(a), "l"(b), "l"(c));
    return d;
}

// ---------------- setup kernels ----------------
__global__ void detect_kernel(const void* ei, int twoE, long long N) {
    int lane = threadIdx.x;
    const long long* p = (const long long*)ei;
    int m = twoE < 64 ? twoE : 64;
    int bad = 0;
#pragma unroll
    for (int r = 0; r < 2; r++) {
        int i = lane + 32 * r;
        if (i < m) {
            long long v = p[i];
            if (v < 0 || v >= N) bad = 1;
        }
    }
    unsigned anybad = __ballot_sync(0xFFFFFFFFu, bad);
    if (lane == 0) g_is64 = (anybad == 0u) ? 1 : 0;
}

// split edge_index + self loops + zero cnt/as1/ad1 (fused)
__global__ void edges_kernel(const void* ei, int E, int N) {
    int i = blockIdx.x * blockDim.x + threadIdx.x;
    int twoE = 2 * E;
    if (i < N) g_cnt[i] = 0;
    if (i < N * H1) { g_as1[i] = 0.f; g_ad1[i] = 0.f; }
    if (i < twoE) {
        int v;
        if (g_is64) v = (int)((const long long*)ei)[i];
        else        v = ((const int*)ei)[i];
        if (i < E) g_src[i] = v;
        else       g_dst[i - E] = v;
    } else if (i < twoE + N) {
        int n = i - twoE;
        g_src[E + n] = n;
        g_dst[E + n] = n;
    }
}

__global__ void wt_kernel(const float* __restrict__ W1) {
    int i = blockIdx.x * blockDim.x + threadIdx.x;
    if (i < F_IN * HC) {
        int k = i / HC, c = i % HC;
        g_Wt[i] = W1[c * F_IN + k];
    }
}

__global__ void hist_kernel(int EA) {
    int e = blockIdx.x * blockDim.x + threadIdx.x;
    if (e < EA) atomicAdd(&g_cnt[g_dst[e]], 1);
}

// hierarchical scan: per-block local exclusive scan + block totals
__global__ void scan1_kernel(int N) {
    __shared__ int sp[SCB];
    int t = threadIdx.x;
    int i = blockIdx.x * SCB + t;
    int val = (i < N) ? g_cnt[i] : 0;
    sp[t] = val;
    __syncthreads();
    for (int off = 1; off < SCB; off <<= 1) {
        int v = (t >= off) ? sp[t - off] : 0;
        __syncthreads();
        sp[t] += v;
        __syncthreads();
    }
    if (i < N) g_rowstart[i] = sp[t] - val;   // local exclusive
    if (t == SCB - 1) g_bsum[blockIdx.x] = sp[t];
}

__global__ void scan2_kernel(int nb) {
    __shared__ int sp[256];
    int t = threadIdx.x;
    int val = (t < nb) ? g_bsum[t] : 0;
    sp[t] = val;
    __syncthreads();
    for (int off = 1; off < 256; off <<= 1) {
        int v = (t >= off) ? sp[t - off] : 0;
        __syncthreads();
        sp[t] += v;
        __syncthreads();
    }
    if (t < nb) g_boff[t] = sp[t] - val;      // exclusive
}

__global__ void scan3_kernel(int N) {
    int i = blockIdx.x * blockDim.x + threadIdx.x;
    if (i < N) {
        int v = g_rowstart[i] + g_boff[i >> 10];
        g_rowstart[i] = v;
        g_fill[i]     = v;
    }
}

__global__ void scatter_kernel(int EA) {
    int e = blockIdx.x * blockDim.x + threadIdx.x;
    if (e >= EA) return;
    int d = g_dst[e];
    int pos = atomicAdd(&g_fill[d], 1);
    g_csr_src[pos] = g_src[e];
}

// ------------- h1 = x @ W1^T : register-tiled 128x128 f32x2, fused att-dots --
__global__ void __launch_bounds__(256, 2) gemm1_kernel(const float* __restrict__ x, int N,
                                                       const float* __restrict__ att_src,
                                                       const float* __restrict__ att_dst) {
    __shared__ float As2[BK * ASTRIDE];   // [k][2n] duplicated pairs {v,v}
    __shared__ float Ws[BK * BN];         // [k][c]
    int t  = threadIdx.x;
    int tx = t & 15;
    int ty = t >> 4;
    int n0 = blockIdx.x * BM;
    int c0 = blockIdx.y * BN;

    u64 acc[8][4];
#pragma unroll
    for (int i = 0; i < 8; i++)
#pragma unroll
        for (int j = 0; j < 4; j++) acc[i][j] = 0ull;

    for (int k0 = 0; k0 < F_IN; k0 += BK) {
        if (k0) __syncthreads();
#pragma unroll
        for (int i = 0; i < 2; i++) {
            int lin  = t + 256 * i;
            int node = lin >> 2;
            int kq   = lin & 3;
            float4 v = make_float4(0.f, 0.f, 0.f, 0.f);
            if (n0 + node < N)
                v = *(const float4*)&x[(n0 + node) * F_IN + k0 + kq * 4];
            float* dst = &As2[(kq * 4) * ASTRIDE + 2 * node];
            *(u64*)(dst + 0 * ASTRIDE) = pack2(v.x, v.x);
            *(u64*)(dst + 1 * ASTRIDE) = pack2(v.y, v.y);
            *(u64*)(dst + 2 * ASTRIDE) = pack2(v.z, v.z);
            *(u64*)(dst + 3 * ASTRIDE) = pack2(v.w, v.w);
        }
#pragma unroll
        for (int i = 0; i < 2; i++) {
            int lin = t + 256 * i;
            int k   = lin >> 5;
            int cq  = lin & 31;
            *(float4*)&Ws[k * BN + cq * 4] =
                *(const float4*)&g_Wt[(k0 + k) * HC + c0 + cq * 4];
        }
        __syncthreads();
#pragma unroll
        for (int k = 0; k < BK; k++) {
            const ulonglong2* ap = (const ulonglong2*)&As2[k * ASTRIDE + ty * 16];
            const ulonglong2* wq = (const ulonglong2*)&Ws[k * BN + tx * 8];
            ulonglong2 A0 = ap[0], A1 = ap[1], A2 = ap[2], A3 = ap[3];
            ulonglong2 W0 = wq[0], W1 = wq[1];
            u64 av[8] = {A0.x, A0.y, A1.x, A1.y, A2.x, A2.y, A3.x, A3.y};
            u64 wv[4] = {W0.x, W0.y, W1.x, W1.y};
#pragma unroll
            for (int i = 0; i < 8; i++)
#pragma unroll
                for (int j = 0; j < 4; j++)
                    acc[i][j] = fma2(wv[j], av[i], acc[i][j]);
        }
    }

    // attention vectors for this thread's 8 columns (single head per thread)
    int cbase = c0 + tx * 8;
    int h = cbase >> 6;
    float avs[8], avd[8];
#pragma unroll
    for (int j = 0; j < 8; j++) { avs[j] = att_src[cbase + j]; avd[j] = att_dst[cbase + j]; }

#pragma unroll
    for (int i = 0; i < 8; i++) {
        int node = n0 + ty * 8 + i;
        float4 f0, f1;
        unpack2(acc[i][0], f0.x, f0.y);
        unpack2(acc[i][1], f0.z, f0.w);
        unpack2(acc[i][2], f1.x, f1.y);
        unpack2(acc[i][3], f1.z, f1.w);
        if (node < N) {
            float* o = &g_h1[node * HC + cbase];
            *(float4*)(o + 0) = f0;
            *(float4*)(o + 4) = f1;
        }
        // partial attention dots (8 cols of one head)
        float s = f0.x * avs[0] + f0.y * avs[1] + f0.z * avs[2] + f0.w * avs[3]
                + f1.x * avs[4] + f1.y * avs[5] + f1.z * avs[6] + f1.w * avs[7];
        float d = f0.x * avd[0] + f0.y * avd[1] + f0.z * avd[2] + f0.w * avd[3]
                + f1.x * avd[4] + f1.y * avd[5] + f1.z * avd[6] + f1.w * avd[7];
        // reduce over 8 lanes sharing one head (tx groups of 8 = lane groups of 8)
        s += __shfl_down_sync(0xFFFFFFFFu, s, 4, 8);
        d += __shfl_down_sync(0xFFFFFFFFu, d, 4, 8);
        s += __shfl_down_sync(0xFFFFFFFFu, s, 2, 8);
        d += __shfl_down_sync(0xFFFFFFFFu, d, 2, 8);
        s += __shfl_down_sync(0xFFFFFFFFu, s, 1, 8);
        d += __shfl_down_sync(0xFFFFFFFFu, d, 1, 8);
        if ((tx & 7) == 0 && node < N) {
            atomicAdd(&g_as1[node * H1 + h], s);
            atomicAdd(&g_ad1[node * H1 + h], d);
        }
    }
}

// ---- fused layer-1 softmax+aggregation+layer-2 projection ----
__global__ void agg1_kernel(const float* __restrict__ b1,
                            const float* __restrict__ W2,
                            const float* __restrict__ att_src2,
                            const float* __restrict__ att_dst2) {
    int n  = blockIdx.x;
    int t  = threadIdx.x;
    int g  = t >> 6;        // edge group 0..3
    int c4 = t & 63;        // float4 channel index
    int h4 = c4 >> 4;       // head of channels c4*4..+3
    int start = g_rowstart[n];
    int deg   = g_cnt[n];

    __shared__ float  sden[4];
    __shared__ float  sad[4];
    __shared__ int    ssrc[CH1];
    __shared__ float  sex[CH1 * 4];
    __shared__ float4 sacc4[256];
    __shared__ float  sr0[8], sr1[8];

    if (t < 4) { sden[t] = 0.f; sad[t] = g_ad1[n * 4 + t]; }
    __syncthreads();

    float4 acc = make_float4(0.f, 0.f, 0.f, 0.f);
    int ec = t >> 2, hh = t & 3;
    for (int e0 = 0; e0 < deg; e0 += CH1) {
        int csz = deg - e0; if (csz > CH1) csz = CH1;
        float ex = 0.f;
        if (ec < csz) {
            int s = g_csr_src[start + e0 + ec];
            if (hh == 0) ssrc[ec] = s;
            ex = __expf(lrelu(g_as1[s * 4 + hh] + sad[hh]));
        }
        sex[t] = ex;
        float p = ex;
        p += __shfl_down_sync(0xFFFFFFFFu, p, 16);
        p += __shfl_down_sync(0xFFFFFFFFu, p, 8);
        p += __shfl_down_sync(0xFFFFFFFFu, p, 4);
        if ((t & 31) < 4) atomicAdd(&sden[hh], p);
        __syncthreads();
        // gather phase: 4-edge unroll -> 4 independent LDG.128 in flight
        int e = g;
        for (; e + 12 < csz; e += 16) {
            int s0 = ssrc[e], s1 = ssrc[e + 4], s2 = ssrc[e + 8], s3 = ssrc[e + 12];
            float x0 = sex[e * 4 + h4];
            float x1 = sex[(e + 4) * 4 + h4];
            float x2 = sex[(e + 8) * 4 + h4];
            float x3 = sex[(e + 12) * 4 + h4];
            float4 v0 = *(const float4*)&g_h1[s0 * HC + c4 * 4];
            float4 v1 = *(const float4*)&g_h1[s1 * HC + c4 * 4];
            float4 v2 = *(const float4*)&g_h1[s2 * HC + c4 * 4];
            float4 v3 = *(const float4*)&g_h1[s3 * HC + c4 * 4];
            acc.x += x0 * v0.x; acc.y += x0 * v0.y; acc.z += x0 * v0.z; acc.w += x0 * v0.w;
            acc.x += x1 * v1.x; acc.y += x1 * v1.y; acc.z += x1 * v1.z; acc.w += x1 * v1.w;
            acc.x += x2 * v2.x; acc.y += x2 * v2.y; acc.z += x2 * v2.z; acc.w += x2 * v2.w;
            acc.x += x3 * v3.x; acc.y += x3 * v3.y; acc.z += x3 * v3.z; acc.w += x3 * v3.w;
        }
        for (; e < csz; e += 4) {
            int s = ssrc[e];
            float coef = sex[e * 4 + h4];
            float4 v = *(const float4*)&g_h1[s * HC + c4 * 4];
            acc.x += coef * v.x; acc.y += coef * v.y;
            acc.z += coef * v.z; acc.w += coef * v.w;
        }
        __syncthreads();
    }
    sacc4[t] = acc;
    __syncthreads();

    const float* sp = (const float*)sacc4;
    float y = sp[t] + sp[256 + t] + sp[512 + t] + sp[768 + t];
    int h = t >> 6;
    y = y / (sden[h] + 1e-16f) + b1[t];
    y = fmaxf(y, 0.f);

    float p0 = y * W2[t];
    float p1 = y * W2[HC + t];
#pragma unroll
    for (int o = 16; o; o >>= 1) {
        p0 += __shfl_down_sync(0xFFFFFFFFu, p0, o);
        p1 += __shfl_down_sync(0xFFFFFFFFu, p1, o);
    }
    if ((t & 31) == 0) { sr0[t >> 5] = p0; sr1[t >> 5] = p1; }
    __syncthreads();
    if (t == 0) {
        float a0 = 0.f, a1 = 0.f;
#pragma unroll
        for (int w = 0; w < 8; w++) { a0 += sr0[w]; a1 += sr1[w]; }
        g_h2[n * 2 + 0] = a0;
        g_h2[n * 2 + 1] = a1;
        g_as2[n] = a0 * att_src2[0] + a1 * att_src2[1];
        g_ad2[n] = a0 * att_dst2[0] + a1 * att_dst2[1];
    }
}

// ---------------- fused layer-2: one warp per destination node --------------
__global__ void agg2_kernel(const float* __restrict__ b2,
                            float* __restrict__ out, int N) {
    int gid  = blockIdx.x * blockDim.x + threadIdx.x;
    int n    = gid >> 5;
    int lane = gid & 31;
    if (n >= N) return;
    int start = g_rowstart[n];
    int deg   = g_cnt[n];
    float adv = g_ad2[n];

    float den = 0.f, a0 = 0.f, a1 = 0.f;
    for (int e = lane; e < deg; e += 32) {
        int s  = g_csr_src[start + e];
        float ex = __expf(lrelu(g_as2[s] + adv));
        den += ex;
        float2 hv = *(const float2*)&g_h2[s * 2];
        a0 += ex * hv.x;
        a1 += ex * hv.y;
    }
#pragma unroll
    for (int o = 16; o; o >>= 1) {
        den += __shfl_xor_sync(0xFFFFFFFFu, den, o);
        a0  += __shfl_xor_sync(0xFFFFFFFFu, a0, o);
        a1  += __shfl_xor_sync(0xFFFFFFFFu, a1, o);
    }
    if (lane == 0) {
        float inv = 1.f / (den + 1e-16f);
        out[n * 2 + 0] = a0 * inv + b2[0];
        out[n * 2 + 1] = a1 * inv + b2[1];
    }
}

// ---------------- launch ----------------
extern "C" void kernel_launch(void* const* d_in, const int* in_sizes, int n_in,
                              void* d_out, int out_size) {
    const float* x        = (const float*)d_in[0];
    const void*  ei       = d_in[1];
    const float* W1       = (const float*)d_in[2];
    const float* att_src1 = (const float*)d_in[3];
    const float* att_dst1 = (const float*)d_in[4];
    const float* b1       = (const float*)d_in[5];
    const float* W2       = (const float*)d_in[6];
    const float* att_src2 = (const float*)d_in[7];
    const float* att_dst2 = (const float*)d_in[8];
    const float* b2       = (const float*)d_in[9];

    int N  = in_sizes[0] / F_IN;
    int E  = in_sizes[1] / 2;
    int EA = E + N;

    const int B = 256;
    int gE = (EA + B - 1) / B;
    int nb = (N + SCB - 1) / SCB;

    detect_kernel<<<1, 32>>>(ei, 2 * E, (long long)N);               // idx 0
    edges_kernel<<<(2 * E + N + B - 1) / B, B>>>(ei, E, N);          // idx 1
    wt_kernel<<<(F_IN * HC + B - 1) / B, B>>>(W1);                   // idx 2

    dim3 gg((N + BM - 1) / BM, HC / BN);
    gemm1_kernel<<<gg, 256>>>(x, N, att_src1, att_dst1);             // idx 3 (profiled)

    hist_kernel<<<gE, B>>>(EA);                                      // idx 4
    scan1_kernel<<<nb, SCB>>>(N);                                    // idx 5
    scan2_kernel<<<1, 256>>>(nb);                                    // idx 6
    scan3_kernel<<<(N + B - 1) / B, B>>>(N);                         // idx 7
    scatter_kernel<<<gE, B>>>(EA);                                   // idx 8

    agg1_kernel<<<N, 256>>>(b1, W2, att_src2, att_dst2);             // idx 9
    agg2_kernel<<<(N * 32 + B - 1) / B, B>>>(b2, (float*)d_out, N);  // idx 10
}

// round 6
// speedup vs baseline: 1.4861x; 1.4861x over previous
#include <cuda_runtime.h>

// Problem constants (shapes fixed by setup_inputs)
#define NMAX   50000
#define EAMAX  850000     // E + N self loops
#define F_IN   128
#define HC     256        // heads*out_ch layer 1
#define H1     4
#define CH1    64         // agg1 edge chunk
#define SCB    1024       // scan block size

// gemm tiling
#define BM 128
#define BN 128
#define BK 16
#define ASTRIDE 260

typedef unsigned long long u64;

// ---------------- scratch (static __device__, allocation-free) ----------------
__device__ float    g_h1[NMAX * HC];
__device__ float    g_Wt[F_IN * HC];       // W1 transposed [k][c]
__device__ float    g_as1[NMAX * H1];
__device__ float    g_ad1[NMAX * H1];
__device__ int      g_src[EAMAX];
__device__ int      g_dst[EAMAX];
__device__ int      g_cnt[NMAX];
__device__ int      g_rowstart[NMAX];
__device__ int      g_fill[NMAX];
__device__ int      g_csr_src[EAMAX];
__device__ int      g_bsum[64];
__device__ int      g_boff[64];
__device__ float    g_h2[NMAX * 2];
__device__ float    g_as2[NMAX];
__device__ float    g_ad2[NMAX];
__device__ int      g_is64;

// ---------------- helpers ----------------
__device__ __forceinline__ float lrelu(float x) { return x > 0.f ? x : 0.2f * x; }

__device__ __forceinline__ u64 pack2(float lo, float hi) {
    u64 r;
    asm("mov.b64 %0, {%1, %2};" : "=l"(r) : "f"(lo), "f"(hi));
    return r;
}
__device__ __forceinline__ void unpack2(u64 v, float& lo, float& hi) {
    asm("mov.b64 {%0, %1}, %2;" : "=f"(lo), "=f"(hi) : "l"(v));
}
__device__ __forceinline__ u64 fma2(u64 a, u64 b, u64 c) {
    u64 d;
    asm("fma.rn.f32x2 %0, %1, %2, %3;" : "=l"(d) : "l"(a), "l"(b), "l"(c));
    return d;
}

// ---------------- setup kernels ----------------
__global__ void detect_kernel(const void* ei, int twoE, long long N) {
    int lane = threadIdx.x;
    const long long* p = (const long long*)ei;
    int m = twoE < 64 ? twoE : 64;
    int bad = 0;
#pragma unroll
    for (int r = 0; r < 2; r++) {
        int i = lane + 32 * r;
        if (i < m) {
            long long v = p[i];
            if (v < 0 || v >= N) bad = 1;
        }
    }
    unsigned anybad = __ballot_sync(0xFFFFFFFFu, bad);
    if (lane == 0) g_is64 = (anybad == 0u) ? 1 : 0;
}

// split edge_index + self loops + zero cnt/as1/ad1 (fused)
__global__ void edges_kernel(const void* ei, int E, int N) {
    int i = blockIdx.x * blockDim.x + threadIdx.x;
    int twoE = 2 * E;
    if (i < N) g_cnt[i] = 0;
    if (i < N * H1) { g_as1[i] = 0.f; g_ad1[i] = 0.f; }
    if (i < twoE) {
        int v;
        if (g_is64) v = (int)((const long long*)ei)[i];
        else        v = ((const int*)ei)[i];
        if (i < E) g_src[i] = v;
        else       g_dst[i - E] = v;
    } else if (i < twoE + N) {
        int n = i - twoE;
        g_src[E + n] = n;
        g_dst[E + n] = n;
    }
}

__global__ void wt_kernel(const float* __restrict__ W1) {
    int i = blockIdx.x * blockDim.x + threadIdx.x;
    if (i < F_IN * HC) {
        int k = i / HC, c = i % HC;
        g_Wt[i] = W1[c * F_IN + k];
    }
}

__global__ void hist_kernel(int EA) {
    int e = blockIdx.x * blockDim.x + threadIdx.x;
    if (e < EA) atomicAdd(&g_cnt[g_dst[e]], 1);
}

// hierarchical scan
__global__ void scan1_kernel(int N) {
    __shared__ int sp[SCB];
    int t = threadIdx.x;
    int i = blockIdx.x * SCB + t;
    int val = (i < N) ? g_cnt[i] : 0;
    sp[t] = val;
    __syncthreads();
    for (int off = 1; off < SCB; off <<= 1) {
        int v = (t >= off) ? sp[t - off] : 0;
        __syncthreads();
        sp[t] += v;
        __syncthreads();
    }
    if (i < N) g_rowstart[i] = sp[t] - val;
    if (t == SCB - 1) g_bsum[blockIdx.x] = sp[t];
}

__global__ void scan2_kernel(int nb) {
    __shared__ int sp[256];
    int t = threadIdx.x;
    int val = (t < nb) ? g_bsum[t] : 0;
    sp[t] = val;
    __syncthreads();
    for (int off = 1; off < 256; off <<= 1) {
        int v = (t >= off) ? sp[t - off] : 0;
        __syncthreads();
        sp[t] += v;
        __syncthreads();
    }
    if (t < nb) g_boff[t] = sp[t] - val;
}

__global__ void scan3_kernel(int N) {
    int i = blockIdx.x * blockDim.x + threadIdx.x;
    if (i < N) {
        int v = g_rowstart[i] + g_boff[i >> 10];
        g_rowstart[i] = v;
        g_fill[i]     = v;
    }
}

__global__ void scatter_kernel(int EA) {
    int e = blockIdx.x * blockDim.x + threadIdx.x;
    if (e >= EA) return;
    int d = g_dst[e];
    int pos = atomicAdd(&g_fill[d], 1);
    g_csr_src[pos] = g_src[e];
}

// ------------- h1 = x @ W1^T : register-tiled 128x128 f32x2 -----------------
// Epilogue computes partial attention dots with PLAIN atomicAdd (no shuffles):
// REDG spread-address ~1 cyc/lane, negligible vs mainloop.
__global__ void __launch_bounds__(256, 2) gemm1_kernel(const float* __restrict__ x, int N,
                                                       const float* __restrict__ att_src,
                                                       const float* __restrict__ att_dst) {
    __shared__ float As2[BK * ASTRIDE];   // [k][2n] duplicated pairs {v,v}
    __shared__ float Ws[BK * BN];         // [k][c]
    int t  = threadIdx.x;
    int tx = t & 15;
    int ty = t >> 4;
    int n0 = blockIdx.x * BM;
    int c0 = blockIdx.y * BN;

    u64 acc[8][4];
#pragma unroll
    for (int i = 0; i < 8; i++)
#pragma unroll
        for (int j = 0; j < 4; j++) acc[i][j] = 0ull;

    for (int k0 = 0; k0 < F_IN; k0 += BK) {
        if (k0) __syncthreads();
#pragma unroll
        for (int i = 0; i < 2; i++) {
            int lin  = t + 256 * i;
            int node = lin >> 2;
            int kq   = lin & 3;
            float4 v = make_float4(0.f, 0.f, 0.f, 0.f);
            if (n0 + node < N)
                v = *(const float4*)&x[(n0 + node) * F_IN + k0 + kq * 4];
            float* dst = &As2[(kq * 4) * ASTRIDE + 2 * node];
            *(u64*)(dst + 0 * ASTRIDE) = pack2(v.x, v.x);
            *(u64*)(dst + 1 * ASTRIDE) = pack2(v.y, v.y);
            *(u64*)(dst + 2 * ASTRIDE) = pack2(v.z, v.z);
            *(u64*)(dst + 3 * ASTRIDE) = pack2(v.w, v.w);
        }
#pragma unroll
        for (int i = 0; i < 2; i++) {
            int lin = t + 256 * i;
            int k   = lin >> 5;
            int cq  = lin & 31;
            *(float4*)&Ws[k * BN + cq * 4] =
                *(const float4*)&g_Wt[(k0 + k) * HC + c0 + cq * 4];
        }
        __syncthreads();
#pragma unroll
        for (int k = 0; k < BK; k++) {
            const ulonglong2* ap = (const ulonglong2*)&As2[k * ASTRIDE + ty * 16];
            const ulonglong2* wq = (const ulonglong2*)&Ws[k * BN + tx * 8];
            ulonglong2 A0 = ap[0], A1 = ap[1], A2 = ap[2], A3 = ap[3];
            ulonglong2 W0 = wq[0], W1 = wq[1];
            u64 av[8] = {A0.x, A0.y, A1.x, A1.y, A2.x, A2.y, A3.x, A3.y};
            u64 wv[4] = {W0.x, W0.y, W1.x, W1.y};
#pragma unroll
            for (int i = 0; i < 8; i++)
#pragma unroll
                for (int j = 0; j < 4; j++)
                    acc[i][j] = fma2(wv[j], av[i], acc[i][j]);
        }
    }

    // epilogue: store + shuffle-free partial attention dots
    int cbase = c0 + tx * 8;
    int h = cbase >> 6;
    const float4* as4 = (const float4*)&att_src[cbase];
    const float4* ad4 = (const float4*)&att_dst[cbase];
    float4 s0 = as4[0], s1 = as4[1];
    float4 d0 = ad4[0], d1 = ad4[1];

#pragma unroll
    for (int i = 0; i < 8; i++) {
        int node = n0 + ty * 8 + i;
        if (node >= N) break;
        float4 f0, f1;
        unpack2(acc[i][0], f0.x, f0.y);
        unpack2(acc[i][1], f0.z, f0.w);
        unpack2(acc[i][2], f1.x, f1.y);
        unpack2(acc[i][3], f1.z, f1.w);
        float* o = &g_h1[node * HC + cbase];
        *(float4*)(o + 0) = f0;
        *(float4*)(o + 4) = f1;
        float s = f0.x * s0.x + f0.y * s0.y + f0.z * s0.z + f0.w * s0.w
                + f1.x * s1.x + f1.y * s1.y + f1.z * s1.z + f1.w * s1.w;
        float d = f0.x * d0.x + f0.y * d0.y + f0.z * d0.z + f0.w * d0.w
                + f1.x * d1.x + f1.y * d1.y + f1.z * d1.z + f1.w * d1.w;
        atomicAdd(&g_as1[node * H1 + h], s);
        atomicAdd(&g_ad1[node * H1 + h], d);
    }
}

// ---- fused layer-1 softmax+aggregation+layer-2 projection ----
__global__ void agg1_kernel(const float* __restrict__ b1,
                            const float* __restrict__ W2,
                            const float* __restrict__ att_src2,
                            const float* __restrict__ att_dst2) {
    int n  = blockIdx.x;
    int t  = threadIdx.x;
    int g  = t >> 6;        // edge group 0..3
    int c4 = t & 63;        // float4 channel index
    int h4 = c4 >> 4;       // head of channels c4*4..+3
    int start = g_rowstart[n];
    int deg   = g_cnt[n];

    __shared__ float  sden[4];
    __shared__ float  sad[4];
    __shared__ int    ssrc[CH1];
    __shared__ float  sex[CH1 * 4];
    __shared__ float4 sacc4[256];
    __shared__ float  sr0[8], sr1[8];

    if (t < 4) { sden[t] = 0.f; sad[t] = g_ad1[n * 4 + t]; }
    __syncthreads();

    float4 acc = make_float4(0.f, 0.f, 0.f, 0.f);
    int ec = t >> 2, hh = t & 3;
    for (int e0 = 0; e0 < deg; e0 += CH1) {
        int csz = deg - e0; if (csz > CH1) csz = CH1;
        float ex = 0.f;
        if (ec < csz) {
            int s = g_csr_src[start + e0 + ec];
            if (hh == 0) ssrc[ec] = s;
            ex = __expf(lrelu(g_as1[s * 4 + hh] + sad[hh]));
        }
        sex[t] = ex;
        float p = ex;
        p += __shfl_down_sync(0xFFFFFFFFu, p, 16);
        p += __shfl_down_sync(0xFFFFFFFFu, p, 8);
        p += __shfl_down_sync(0xFFFFFFFFu, p, 4);
        if ((t & 31) < 4) atomicAdd(&sden[hh], p);
        __syncthreads();
        // gather: 4-edge unroll -> 4 independent LDG.128 in flight
        int e = g;
        for (; e + 12 < csz; e += 16) {
            int s0 = ssrc[e], s1 = ssrc[e + 4], s2 = ssrc[e + 8], s3 = ssrc[e + 12];
            float x0 = sex[e * 4 + h4];
            float x1 = sex[(e + 4) * 4 + h4];
            float x2 = sex[(e + 8) * 4 + h4];
            float x3 = sex[(e + 12) * 4 + h4];
            float4 v0 = *(const float4*)&g_h1[s0 * HC + c4 * 4];
            float4 v1 = *(const float4*)&g_h1[s1 * HC + c4 * 4];
            float4 v2 = *(const float4*)&g_h1[s2 * HC + c4 * 4];
            float4 v3 = *(const float4*)&g_h1[s3 * HC + c4 * 4];
            acc.x += x0 * v0.x; acc.y += x0 * v0.y; acc.z += x0 * v0.z; acc.w += x0 * v0.w;
            acc.x += x1 * v1.x; acc.y += x1 * v1.y; acc.z += x1 * v1.z; acc.w += x1 * v1.w;
            acc.x += x2 * v2.x; acc.y += x2 * v2.y; acc.z += x2 * v2.z; acc.w += x2 * v2.w;
            acc.x += x3 * v3.x; acc.y += x3 * v3.y; acc.z += x3 * v3.z; acc.w += x3 * v3.w;
        }
        for (; e < csz; e += 4) {
            int s = ssrc[e];
            float coef = sex[e * 4 + h4];
            float4 v = *(const float4*)&g_h1[s * HC + c4 * 4];
            acc.x += coef * v.x; acc.y += coef * v.y;
            acc.z += coef * v.z; acc.w += coef * v.w;
        }
        __syncthreads();
    }
    sacc4[t] = acc;
    __syncthreads();

    const float* sp = (const float*)sacc4;
    float y = sp[t] + sp[256 + t] + sp[512 + t] + sp[768 + t];
    int h = t >> 6;
    y = y / (sden[h] + 1e-16f) + b1[t];
    y = fmaxf(y, 0.f);

    float p0 = y * W2[t];
    float p1 = y * W2[HC + t];
#pragma unroll
    for (int o = 16; o; o >>= 1) {
        p0 += __shfl_down_sync(0xFFFFFFFFu, p0, o);
        p1 += __shfl_down_sync(0xFFFFFFFFu, p1, o);
    }
    if ((t & 31) == 0) { sr0[t >> 5] = p0; sr1[t >> 5] = p1; }
    __syncthreads();
    if (t == 0) {
        float a0 = 0.f, a1 = 0.f;
#pragma unroll
        for (int w = 0; w < 8; w++) { a0 += sr0[w]; a1 += sr1[w]; }
        g_h2[n * 2 + 0] = a0;
        g_h2[n * 2 + 1] = a1;
        g_as2[n] = a0 * att_src2[0] + a1 * att_src2[1];
        g_ad2[n] = a0 * att_dst2[0] + a1 * att_dst2[1];
    }
}

// ---------------- fused layer-2: one warp per destination node --------------
__global__ void agg2_kernel(const float* __restrict__ b2,
                            float* __restrict__ out, int N) {
    int gid  = blockIdx.x * blockDim.x + threadIdx.x;
    int n    = gid >> 5;
    int lane = gid & 31;
    if (n >= N) return;
    int start = g_rowstart[n];
    int deg   = g_cnt[n];
    float adv = g_ad2[n];

    float den = 0.f, a0 = 0.f, a1 = 0.f;
    for (int e = lane; e < deg; e += 32) {
        int s  = g_csr_src[start + e];
        float ex = __expf(lrelu(g_as2[s] + adv));
        den += ex;
        float2 hv = *(const float2*)&g_h2[s * 2];
        a0 += ex * hv.x;
        a1 += ex * hv.y;
    }
#pragma unroll
    for (int o = 16; o; o >>= 1) {
        den += __shfl_xor_sync(0xFFFFFFFFu, den, o);
        a0  += __shfl_xor_sync(0xFFFFFFFFu, a0, o);
        a1  += __shfl_xor_sync(0xFFFFFFFFu, a1, o);
    }
    if (lane == 0) {
        float inv = 1.f / (den + 1e-16f);
        out[n * 2 + 0] = a0 * inv + b2[0];
        out[n * 2 + 1] = a1 * inv + b2[1];
    }
}

// ---------------- launch ----------------
extern "C" void kernel_launch(void* const* d_in, const int* in_sizes, int n_in,
                              void* d_out, int out_size) {
    const float* x        = (const float*)d_in[0];
    const void*  ei       = d_in[1];
    const float* W1       = (const float*)d_in[2];
    const float* att_src1 = (const float*)d_in[3];
    const float* att_dst1 = (const float*)d_in[4];
    const float* b1       = (const float*)d_in[5];
    const float* W2       = (const float*)d_in[6];
    const float* att_src2 = (const float*)d_in[7];
    const float* att_dst2 = (const float*)d_in[8];
    const float* b2       = (const float*)d_in[9];

    int N  = in_sizes[0] / F_IN;
    int E  = in_sizes[1] / 2;
    int EA = E + N;

    const int B = 256;
    int gE = (EA + B - 1) / B;
    int nb = (N + SCB - 1) / SCB;

    detect_kernel<<<1, 32>>>(ei, 2 * E, (long long)N);               // idx 0
    edges_kernel<<<(2 * E + N + B - 1) / B, B>>>(ei, E, N);          // idx 1
    wt_kernel<<<(F_IN * HC + B - 1) / B, B>>>(W1);                   // idx 2

    dim3 gg((N + BM - 1) / BM, HC / BN);
    gemm1_kernel<<<gg, 256>>>(x, N, att_src1, att_dst1);             // idx 3 (profiled)

    hist_kernel<<<gE, B>>>(EA);                                      // idx 4
    scan1_kernel<<<nb, SCB>>>(N);                                    // idx 5
    scan2_kernel<<<1, 256>>>(nb);                                    // idx 6
    scan3_kernel<<<(N + B - 1) / B, B>>>(N);                         // idx 7
    scatter_kernel<<<gE, B>>>(EA);                                   // idx 8

    agg1_kernel<<<N, 256>>>(b1, W2, att_src2, att_dst2);             // idx 9
    agg2_kernel<<<(N * 32 + B - 1) / B, B>>>(b2, (float*)d_out, N);  // idx 10
}

// round 7
// speedup vs baseline: 1.9334x; 1.3010x over previous
#include <cuda_runtime.h>

// Problem constants (shapes fixed by setup_inputs)
#define NMAX   50000
#define EAMAX  850000     // E + N self loops
#define F_IN   128
#define HC     256        // heads*out_ch layer 1
#define H1     4
#define SCB    1024       // scan block size

// gemm tiling
#define BM 128
#define BN 128
#define BK 16
#define ASTRIDE 260

typedef unsigned long long u64;

// ---------------- scratch (static __device__, allocation-free) ----------------
__device__ float    g_h1[NMAX * HC];
__device__ float    g_Wt[F_IN * HC];       // W1 transposed [k][c]
__device__ float    g_as1[NMAX * H1];
__device__ float    g_ad1[NMAX * H1];
__device__ int      g_src[EAMAX];
__device__ int      g_dst[EAMAX];
__device__ int      g_cnt[NMAX];
__device__ int      g_rowstart[NMAX];
__device__ int      g_fill[NMAX];
__device__ int      g_csr_src[EAMAX];
__device__ int      g_bsum[64];
__device__ int      g_boff[64];
__device__ float    g_h2[NMAX * 2];
__device__ float    g_as2[NMAX];
__device__ float    g_ad2[NMAX];
__device__ int      g_is64;

// ---------------- helpers ----------------
__device__ __forceinline__ float lrelu(float x) { return x > 0.f ? x : 0.2f * x; }

__device__ __forceinline__ u64 pack2(float lo, float hi) {
    u64 r;
    asm("mov.b64 %0, {%1, %2};" : "=l"(r) : "f"(lo), "f"(hi));
    return r;
}
__device__ __forceinline__ void unpack2(u64 v, float& lo, float& hi) {
    asm("mov.b64 {%0, %1}, %2;" : "=f"(lo), "=f"(hi) : "l"(v));
}
__device__ __forceinline__ u64 fma2(u64 a, u64 b, u64 c) {
    u64 d;
    asm("fma.rn.f32x2 %0, %1, %2, %3;" : "=l"(d) : "l"(a), "l"(b), "l"(c));
    return d;
}

// ---------------- setup kernels ----------------
__global__ void detect_kernel(const void* ei, int twoE, long long N) {
    int lane = threadIdx.x;
    const long long* p = (const long long*)ei;
    int m = twoE < 64 ? twoE : 64;
    int bad = 0;
#pragma unroll
    for (int r = 0; r < 2; r++) {
        int i = lane + 32 * r;
        if (i < m) {
            long long v = p[i];
            if (v < 0 || v >= N) bad = 1;
        }
    }
    unsigned anybad = __ballot_sync(0xFFFFFFFFu, bad);
    if (lane == 0) g_is64 = (anybad == 0u) ? 1 : 0;
}

__global__ void zerocnt_kernel(int N) {
    int i = blockIdx.x * blockDim.x + threadIdx.x;
    if (i < N) g_cnt[i] = 0;
}

// Wt transpose + zero as1/ad1 (branch A prologue)
__global__ void wtzero_kernel(const float* __restrict__ W1, int N) {
    int i = blockIdx.x * blockDim.x + threadIdx.x;
    if (i < F_IN * HC) {
        int k = i / HC, c = i % HC;
        g_Wt[i] = W1[c * F_IN + k];
    }
    if (i < N * H1) { g_as1[i] = 0.f; g_ad1[i] = 0.f; }
}

// split edge_index + self loops + fused dst histogram
__global__ void edges_hist_kernel(const void* ei, int E, int N) {
    int i = blockIdx.x * blockDim.x + threadIdx.x;
    int twoE = 2 * E;
    if (i < twoE) {
        int v;
        if (g_is64) v = (int)((const long long*)ei)[i];
        else        v = ((const int*)ei)[i];
        if (i < E) g_src[i] = v;
        else {
            g_dst[i - E] = v;
            atomicAdd(&g_cnt[v], 1);
        }
    } else if (i < twoE + N) {
        int n = i - twoE;
        g_src[E + n] = n;
        g_dst[E + n] = n;
        atomicAdd(&g_cnt[n], 1);
    }
}

// hierarchical scan
__global__ void scan1_kernel(int N) {
    __shared__ int sp[SCB];
    int t = threadIdx.x;
    int i = blockIdx.x * SCB + t;
    int val = (i < N) ? g_cnt[i] : 0;
    sp[t] = val;
    __syncthreads();
    for (int off = 1; off < SCB; off <<= 1) {
        int v = (t >= off) ? sp[t - off] : 0;
        __syncthreads();
        sp[t] += v;
        __syncthreads();
    }
    if (i < N) g_rowstart[i] = sp[t] - val;
    if (t == SCB - 1) g_bsum[blockIdx.x] = sp[t];
}

__global__ void scan2_kernel(int nb) {
    __shared__ int sp[256];
    int t = threadIdx.x;
    int val = (t < nb) ? g_bsum[t] : 0;
    sp[t] = val;
    __syncthreads();
    for (int off = 1; off < 256; off <<= 1) {
        int v = (t >= off) ? sp[t - off] : 0;
        __syncthreads();
        sp[t] += v;
        __syncthreads();
    }
    if (t < nb) g_boff[t] = sp[t] - val;
}

__global__ void scan3_kernel(int N) {
    int i = blockIdx.x * blockDim.x + threadIdx.x;
    if (i < N) {
        int v = g_rowstart[i] + g_boff[i >> 10];
        g_rowstart[i] = v;
        g_fill[i]     = v;
    }
}

__global__ void scatter_kernel(int EA) {
    int e = blockIdx.x * blockDim.x + threadIdx.x;
    if (e >= EA) return;
    int d = g_dst[e];
    int pos = atomicAdd(&g_fill[d], 1);
    g_csr_src[pos] = g_src[e];
}

// ------------- h1 = x @ W1^T : register-tiled 128x128 f32x2 -----------------
// Epilogue: shuffle-free partial attention dots via spread-address atomicAdd.
__global__ void __launch_bounds__(256, 2) gemm1_kernel(const float* __restrict__ x, int N,
                                                       const float* __restrict__ att_src,
                                                       const float* __restrict__ att_dst) {
    __shared__ float As2[BK * ASTRIDE];   // [k][2n] duplicated pairs {v,v}
    __shared__ float Ws[BK * BN];         // [k][c]
    int t  = threadIdx.x;
    int tx = t & 15;
    int ty = t >> 4;
    int n0 = blockIdx.x * BM;
    int c0 = blockIdx.y * BN;

    u64 acc[8][4];
#pragma unroll
    for (int i = 0; i < 8; i++)
#pragma unroll
        for (int j = 0; j < 4; j++) acc[i][j] = 0ull;

    for (int k0 = 0; k0 < F_IN; k0 += BK) {
        if (k0) __syncthreads();
#pragma unroll
        for (int i = 0; i < 2; i++) {
            int lin  = t + 256 * i;
            int node = lin >> 2;
            int kq   = lin & 3;
            float4 v = make_float4(0.f, 0.f, 0.f, 0.f);
            if (n0 + node < N)
                v = *(const float4*)&x[(n0 + node) * F_IN + k0 + kq * 4];
            float* dst = &As2[(kq * 4) * ASTRIDE + 2 * node];
            *(u64*)(dst + 0 * ASTRIDE) = pack2(v.x, v.x);
            *(u64*)(dst + 1 * ASTRIDE) = pack2(v.y, v.y);
            *(u64*)(dst + 2 * ASTRIDE) = pack2(v.z, v.z);
            *(u64*)(dst + 3 * ASTRIDE) = pack2(v.w, v.w);
        }
#pragma unroll
        for (int i = 0; i < 2; i++) {
            int lin = t + 256 * i;
            int k   = lin >> 5;
            int cq  = lin & 31;
            *(float4*)&Ws[k * BN + cq * 4] =
                *(const float4*)&g_Wt[(k0 + k) * HC + c0 + cq * 4];
        }
        __syncthreads();
#pragma unroll
        for (int k = 0; k < BK; k++) {
            const ulonglong2* ap = (const ulonglong2*)&As2[k * ASTRIDE + ty * 16];
            const ulonglong2* wq = (const ulonglong2*)&Ws[k * BN + tx * 8];
            ulonglong2 A0 = ap[0], A1 = ap[1], A2 = ap[2], A3 = ap[3];
            ulonglong2 W0 = wq[0], W1 = wq[1];
            u64 av[8] = {A0.x, A0.y, A1.x, A1.y, A2.x, A2.y, A3.x, A3.y};
            u64 wv[4] = {W0.x, W0.y, W1.x, W1.y};
#pragma unroll
            for (int i = 0; i < 8; i++)
#pragma unroll
                for (int j = 0; j < 4; j++)
                    acc[i][j] = fma2(wv[j], av[i], acc[i][j]);
        }
    }

    int cbase = c0 + tx * 8;
    int h = cbase >> 6;
    const float4* as4 = (const float4*)&att_src[cbase];
    const float4* ad4 = (const float4*)&att_dst[cbase];
    float4 s0 = as4[0], s1 = as4[1];
    float4 d0 = ad4[0], d1 = ad4[1];

#pragma unroll
    for (int i = 0; i < 8; i++) {
        int node = n0 + ty * 8 + i;
        if (node >= N) break;
        float4 f0, f1;
        unpack2(acc[i][0], f0.x, f0.y);
        unpack2(acc[i][1], f0.z, f0.w);
        unpack2(acc[i][2], f1.x, f1.y);
        unpack2(acc[i][3], f1.z, f1.w);
        float* o = &g_h1[node * HC + cbase];
        *(float4*)(o + 0) = f0;
        *(float4*)(o + 4) = f1;
        float s = f0.x * s0.x + f0.y * s0.y + f0.z * s0.z + f0.w * s0.w
                + f1.x * s1.x + f1.y * s1.y + f1.z * s1.z + f1.w * s1.w;
        float d = f0.x * d0.x + f0.y * d0.y + f0.z * d0.z + f0.w * d0.w
                + f1.x * d1.x + f1.y * d1.y + f1.z * d1.z + f1.w * d1.w;
        atomicAdd(&g_as1[node * H1 + h], s);
        atomicAdd(&g_ad1[node * H1 + h], d);
    }
}

// ---- fused layer-1 softmax+aggregation+layer-2 projection -------------------
// One WARP per destination node, barrier-free. Lane = 8 contiguous channels
// (one head). Per-edge exp computed in-lane; den accumulated per-lane.
__global__ void agg1_kernel(const float* __restrict__ b1,
                            const float* __restrict__ W2,
                            const float* __restrict__ att_src2,
                            const float* __restrict__ att_dst2, int N) {
    int gid  = blockIdx.x * blockDim.x + threadIdx.x;
    int n    = gid >> 5;
    int lane = gid & 31;
    if (n >= N) return;
    int start = g_rowstart[n];
    int deg   = g_cnt[n];
    int cbase = lane * 8;
    int h     = lane >> 3;
    float ad  = g_ad1[n * 4 + h];

    float4 A0 = make_float4(0.f, 0.f, 0.f, 0.f);
    float4 A1 = make_float4(0.f, 0.f, 0.f, 0.f);
    float den = 0.f;

    int e = 0;
    for (; e + 2 <= deg; e += 2) {
        int s0i = g_csr_src[start + e];
        int s1i = g_csr_src[start + e + 1];
        float a0 = g_as1[s0i * 4 + h];
        float a1 = g_as1[s1i * 4 + h];
        const float4* p0 = (const float4*)&g_h1[s0i * HC + cbase];
        const float4* p1 = (const float4*)&g_h1[s1i * HC + cbase];
        float4 v00 = p0[0], v01 = p0[1];
        float4 v10 = p1[0], v11 = p1[1];
        float x0 = __expf(lrelu(a0 + ad));
        float x1 = __expf(lrelu(a1 + ad));
        den += x0 + x1;
        A0.x += x0 * v00.x; A0.y += x0 * v00.y; A0.z += x0 * v00.z; A0.w += x0 * v00.w;
        A1.x += x0 * v01.x; A1.y += x0 * v01.y; A1.z += x0 * v01.z; A1.w += x0 * v01.w;
        A0.x += x1 * v10.x; A0.y += x1 * v10.y; A0.z += x1 * v10.z; A0.w += x1 * v10.w;
        A1.x += x1 * v11.x; A1.y += x1 * v11.y; A1.z += x1 * v11.z; A1.w += x1 * v11.w;
    }
    if (e < deg) {
        int s0i = g_csr_src[start + e];
        float a0 = g_as1[s0i * 4 + h];
        const float4* p0 = (const float4*)&g_h1[s0i * HC + cbase];
        float4 v00 = p0[0], v01 = p0[1];
        float x0 = __expf(lrelu(a0 + ad));
        den += x0;
        A0.x += x0 * v00.x; A0.y += x0 * v00.y; A0.z += x0 * v00.z; A0.w += x0 * v00.w;
        A1.x += x0 * v01.x; A1.y += x0 * v01.y; A1.z += x0 * v01.z; A1.w += x0 * v01.w;
    }

    float inv = 1.f / (den + 1e-16f);
    const float4* b4 = (const float4*)&b1[cbase];
    float4 bb0 = b4[0], bb1 = b4[1];
    float4 y0, y1;
    y0.x = fmaxf(A0.x * inv + bb0.x, 0.f);
    y0.y = fmaxf(A0.y * inv + bb0.y, 0.f);
    y0.z = fmaxf(A0.z * inv + bb0.z, 0.f);
    y0.w = fmaxf(A0.w * inv + bb0.w, 0.f);
    y1.x = fmaxf(A1.x * inv + bb1.x, 0.f);
    y1.y = fmaxf(A1.y * inv + bb1.y, 0.f);
    y1.z = fmaxf(A1.z * inv + bb1.z, 0.f);
    y1.w = fmaxf(A1.w * inv + bb1.w, 0.f);

    const float4* w0q = (const float4*)&W2[cbase];
    const float4* w1q = (const float4*)&W2[HC + cbase];
    float4 wa0 = w0q[0], wa1 = w0q[1];
    float4 wb0 = w1q[0], wb1 = w1q[1];
    float p0 = y0.x * wa0.x + y0.y * wa0.y + y0.z * wa0.z + y0.w * wa0.w
             + y1.x * wa1.x + y1.y * wa1.y + y1.z * wa1.z + y1.w * wa1.w;
    float p1 = y0.x * wb0.x + y0.y * wb0.y + y0.z * wb0.z + y0.w * wb0.w
             + y1.x * wb1.x + y1.y * wb1.y + y1.z * wb1.z + y1.w * wb1.w;
#pragma unroll
    for (int o = 16; o; o >>= 1) {
        p0 += __shfl_down_sync(0xFFFFFFFFu, p0, o);
        p1 += __shfl_down_sync(0xFFFFFFFFu, p1, o);
    }
    if (lane == 0) {
        g_h2[n * 2 + 0] = p0;
        g_h2[n * 2 + 1] = p1;
        g_as2[n] = p0 * att_src2[0] + p1 * att_src2[1];
        g_ad2[n] = p0 * att_dst2[0] + p1 * att_dst2[1];
    }
}

// ---------------- fused layer-2: one warp per destination node --------------
__global__ void agg2_kernel(const float* __restrict__ b2,
                            float* __restrict__ out, int N) {
    int gid  = blockIdx.x * blockDim.x + threadIdx.x;
    int n    = gid >> 5;
    int lane = gid & 31;
    if (n >= N) return;
    int start = g_rowstart[n];
    int deg   = g_cnt[n];
    float adv = g_ad2[n];

    float den = 0.f, a0 = 0.f, a1 = 0.f;
    for (int e = lane; e < deg; e += 32) {
        int s  = g_csr_src[start + e];
        float ex = __expf(lrelu(g_as2[s] + adv));
        den += ex;
        float2 hv = *(const float2*)&g_h2[s * 2];
        a0 += ex * hv.x;
        a1 += ex * hv.y;
    }
#pragma unroll
    for (int o = 16; o; o >>= 1) {
        den += __shfl_xor_sync(0xFFFFFFFFu, den, o);
        a0  += __shfl_xor_sync(0xFFFFFFFFu, a0, o);
        a1  += __shfl_xor_sync(0xFFFFFFFFu, a1, o);
    }
    if (lane == 0) {
        float inv = 1.f / (den + 1e-16f);
        out[n * 2 + 0] = a0 * inv + b2[0];
        out[n * 2 + 1] = a1 * inv + b2[1];
    }
}

// ---------------- launch ----------------
extern "C" void kernel_launch(void* const* d_in, const int* in_sizes, int n_in,
                              void* d_out, int out_size) {
    const float* x        = (const float*)d_in[0];
    const void*  ei       = d_in[1];
    const float* W1       = (const float*)d_in[2];
    const float* att_src1 = (const float*)d_in[3];
    const float* att_dst1 = (const float*)d_in[4];
    const float* b1       = (const float*)d_in[5];
    const float* W2       = (const float*)d_in[6];
    const float* att_src2 = (const float*)d_in[7];
    const float* att_dst2 = (const float*)d_in[8];
    const float* b2       = (const float*)d_in[9];

    int N  = in_sizes[0] / F_IN;
    int E  = in_sizes[1] / 2;
    int EA = E + N;

    const int B = 256;
    int gE = (EA + B - 1) / B;
    int nb = (N + SCB - 1) / SCB;

    // Side stream + events for forked capture (created once, host-side only).
    static cudaStream_t sB = 0;
    static cudaEvent_t  ev0 = 0, evB = 0;
    if (!sB) {
        cudaStreamCreateWithFlags(&sB, cudaStreamNonBlocking);
        cudaEventCreateWithFlags(&ev0, cudaEventDisableTiming);
        cudaEventCreateWithFlags(&evB, cudaEventDisableTiming);
    }

    // -------- main stream (0): edge-side prologue --------
    detect_kernel<<<1, 32>>>(ei, 2 * E, (long long)N);                     // [0]
    zerocnt_kernel<<<(N + B - 1) / B, B>>>(N);                             // [1]

    // -------- fork: branch A (wt + gemm) on sB --------
    cudaEventRecord(ev0, 0);
    cudaStreamWaitEvent(sB, ev0, 0);
    wtzero_kernel<<<(N * H1 + B - 1) / B, B, 0, sB>>>(W1, N);              // [2]
    dim3 gg((N + BM - 1) / BM, HC / BN);
    gemm1_kernel<<<gg, 256, 0, sB>>>(x, N, att_src1, att_dst1);            // [3] (profiled)
    cudaEventRecord(evB, sB);

    // -------- branch B: CSR build on stream 0 (overlaps gemm) --------
    edges_hist_kernel<<<(2 * E + N + B - 1) / B, B>>>(ei, E, N);           // [4]
    scan1_kernel<<<nb, SCB>>>(N);                                          // [5]
    scan2_kernel<<<1, 256>>>(nb);                                          // [6]
    scan3_kernel<<<(N + B - 1) / B, B>>>(N);                               // [7]
    scatter_kernel<<<gE, B>>>(EA);                                         // [8]

    // -------- join + aggregation --------
    cudaStreamWaitEvent(0, evB, 0);
    agg1_kernel<<<(N * 32 + B - 1) / B, B>>>(b1, W2, att_src2, att_dst2, N); // [9]
    agg2_kernel<<<(N * 32 + B - 1) / B, B>>>(b2, (float*)d_out, N);          // [10]
}

// round 8
// speedup vs baseline: 2.0553x; 1.0630x over previous
#include <cuda_runtime.h>
#include <cstdint>

// Problem constants (shapes fixed by setup_inputs)
#define NMAX   50000
#define EAMAX  850000     // E + N self loops
#define F_IN   128
#define HC     256        // heads*out_ch layer 1
#define H1     4
#define SCB    1024       // scan block size

// gemm tiling
#define BM 128
#define BN 128
#define BK 8              // k-chunk (16 chunks, double-buffered)
#define ASTRIDE 260       // floats per As2 row: 2*BM + 4 pad

typedef unsigned long long u64;

// ---------------- scratch (static __device__, allocation-free) ----------------
__device__ float    g_h1[NMAX * HC];
__device__ float    g_Wt[F_IN * HC];       // W1 transposed [k][c]
__device__ float    g_as1[NMAX * H1];
__device__ float    g_ad1[NMAX * H1];
__device__ int      g_src[EAMAX];
__device__ int      g_dst[EAMAX];
__device__ int      g_cnt[NMAX];
__device__ int      g_rowstart[NMAX];
__device__ int      g_fill[NMAX];
__device__ int      g_csr_src[EAMAX];
__device__ int      g_bsum[64];
__device__ int      g_boff[64];
__device__ float    g_h2[NMAX * 2];
__device__ float    g_as2[NMAX];
__device__ float    g_ad2[NMAX];
__device__ int      g_is64;

// ---------------- helpers ----------------
__device__ __forceinline__ float lrelu(float x) { return x > 0.f ? x : 0.2f * x; }

__device__ __forceinline__ u64 pack2(float lo, float hi) {
    u64 r;
    asm("mov.b64 %0, {%1, %2};" : "=l"(r) : "f"(lo), "f"(hi));
    return r;
}
__device__ __forceinline__ void unpack2(u64 v, float& lo, float& hi) {
    asm("mov.b64 {%0, %1}, %2;" : "=f"(lo), "=f"(hi) : "l"(v));
}
__device__ __forceinline__ u64 fma2(u64 a, u64 b, u64 c) {
    u64 d;
    asm("fma.rn.f32x2 %0, %1, %2, %3;" : "=l"(d) : "l"(a), "l"(b), "l"(c));
    return d;
}
__device__ __forceinline__ uint32_t sm2u32(const void* p) {
    return (uint32_t)__cvta_generic_to_shared(p);
}
__device__ __forceinline__ void cpasync16(uint32_t smem, const void* g) {
    asm volatile("cp.async.ca.shared.global [%0], [%1], 16;" :: "r"(smem), "l"(g));
}
#define CPCOMMIT() asm volatile("cp.async.commit_group;")
#define CPWAIT0()  asm volatile("cp.async.wait_group 0;")

// ---------------- setup kernels ----------------
__global__ void detect_kernel(const void* ei, int twoE, long long N) {
    int lane = threadIdx.x;
    const long long* p = (const long long*)ei;
    int m = twoE < 64 ? twoE : 64;
    int bad = 0;
#pragma unroll
    for (int r = 0; r < 2; r++) {
        int i = lane + 32 * r;
        if (i < m) {
            long long v = p[i];
            if (v < 0 || v >= N) bad = 1;
        }
    }
    unsigned anybad = __ballot_sync(0xFFFFFFFFu, bad);
    if (lane == 0) g_is64 = (anybad == 0u) ? 1 : 0;
}

__global__ void zerocnt_kernel(int N) {
    int i = blockIdx.x * blockDim.x + threadIdx.x;
    if (i < N) g_cnt[i] = 0;
}

// Wt transpose + zero as1/ad1 (branch A prologue)
__global__ void wtzero_kernel(const float* __restrict__ W1, int N) {
    int i = blockIdx.x * blockDim.x + threadIdx.x;
    if (i < F_IN * HC) {
        int k = i / HC, c = i % HC;
        g_Wt[i] = W1[c * F_IN + k];
    }
    if (i < N * H1) { g_as1[i] = 0.f; g_ad1[i] = 0.f; }
}

// split edge_index + self loops + fused dst histogram
__global__ void edges_hist_kernel(const void* ei, int E, int N) {
    int i = blockIdx.x * blockDim.x + threadIdx.x;
    int twoE = 2 * E;
    if (i < twoE) {
        int v;
        if (g_is64) v = (int)((const long long*)ei)[i];
        else        v = ((const int*)ei)[i];
        if (i < E) g_src[i] = v;
        else {
            g_dst[i - E] = v;
            atomicAdd(&g_cnt[v], 1);
        }
    } else if (i < twoE + N) {
        int n = i - twoE;
        g_src[E + n] = n;
        g_dst[E + n] = n;
        atomicAdd(&g_cnt[n], 1);
    }
}

// hierarchical scan
__global__ void scan1_kernel(int N) {
    __shared__ int sp[SCB];
    int t = threadIdx.x;
    int i = blockIdx.x * SCB + t;
    int val = (i < N) ? g_cnt[i] : 0;
    sp[t] = val;
    __syncthreads();
    for (int off = 1; off < SCB; off <<= 1) {
        int v = (t >= off) ? sp[t - off] : 0;
        __syncthreads();
        sp[t] += v;
        __syncthreads();
    }
    if (i < N) g_rowstart[i] = sp[t] - val;
    if (t == SCB - 1) g_bsum[blockIdx.x] = sp[t];
}

__global__ void scan2_kernel(int nb) {
    __shared__ int sp[256];
    int t = threadIdx.x;
    int val = (t < nb) ? g_bsum[t] : 0;
    sp[t] = val;
    __syncthreads();
    for (int off = 1; off < 256; off <<= 1) {
        int v = (t >= off) ? sp[t - off] : 0;
        __syncthreads();
        sp[t] += v;
        __syncthreads();
    }
    if (t < nb) g_boff[t] = sp[t] - val;
}

__global__ void scan3_kernel(int N) {
    int i = blockIdx.x * blockDim.x + threadIdx.x;
    if (i < N) {
        int v = g_rowstart[i] + g_boff[i >> 10];
        g_rowstart[i] = v;
        g_fill[i]     = v;
    }
}

__global__ void scatter_kernel(int EA) {
    int e = blockIdx.x * blockDim.x + threadIdx.x;
    if (e >= EA) return;
    int d = g_dst[e];
    int pos = atomicAdd(&g_fill[d], 1);
    g_csr_src[pos] = g_src[e];
}

// ------------- h1 = x @ W1^T : 128x128 f32x2, double-buffered pipeline ------
// W staged via cp.async (LDGSTS), A via register prefetch; one sync/iteration.
__global__ void __launch_bounds__(256, 2) gemm1_kernel(const float* __restrict__ x, int N,
                                                       const float* __restrict__ att_src,
                                                       const float* __restrict__ att_dst) {
    __shared__ float As2[2][BK * ASTRIDE];   // [k][2n] duplicated pairs {v,v}
    __shared__ float Ws[2][BK * BN];         // [k][c]
    int t  = threadIdx.x;
    int tx = t & 15;
    int ty = t >> 4;
    int n0 = blockIdx.x * BM;
    int c0 = blockIdx.y * BN;

    // staging task assignment (1 task each per chunk)
    int nodeA = t >> 1, kqA = t & 1;                 // A: 128 nodes x 2 kquads
    int kW = t >> 5,    cqW = t & 31;                // W: 8 k x 32 cquads
    bool aok = (n0 + nodeA) < N;
    const float4* xsrc = (const float4*)&x[(n0 + nodeA) * F_IN + kqA * 4];
    const float*  wsrc = &g_Wt[kW * HC + c0 + cqW * 4];
    float* adst0 = &As2[0][(kqA * 4) * ASTRIDE + 2 * nodeA];
    float* adst1 = &As2[1][(kqA * 4) * ASTRIDE + 2 * nodeA];
    uint32_t wdst0 = sm2u32(&Ws[0][kW * BN + cqW * 4]);
    uint32_t wdst1 = sm2u32(&Ws[1][kW * BN + cqW * 4]);

    u64 acc[8][4];
#pragma unroll
    for (int i = 0; i < 8; i++)
#pragma unroll
        for (int j = 0; j < 4; j++) acc[i][j] = 0ull;

    // prologue: stage chunk 0 into buffer 0
    {
        cpasync16(wdst0, wsrc);
        CPCOMMIT();
        float4 v = make_float4(0.f, 0.f, 0.f, 0.f);
        if (aok) v = xsrc[0];
        *(u64*)(adst0 + 0 * ASTRIDE) = pack2(v.x, v.x);
        *(u64*)(adst0 + 1 * ASTRIDE) = pack2(v.y, v.y);
        *(u64*)(adst0 + 2 * ASTRIDE) = pack2(v.z, v.z);
        *(u64*)(adst0 + 3 * ASTRIDE) = pack2(v.w, v.w);
        CPWAIT0();
        __syncthreads();
    }

    for (int it = 0; it < 16; it++) {
        int cur = it & 1;
        float4 nv = make_float4(0.f, 0.f, 0.f, 0.f);
        if (it < 15) {
            int k0 = (it + 1) * BK;
            cpasync16(cur ? wdst0 : wdst1, wsrc + k0 * HC);
            CPCOMMIT();
            if (aok) nv = xsrc[k0 >> 2];       // xsrc is float4*, k0/4 quads
        }
        const float* Ab = As2[cur];
        const float* Wb = Ws[cur];
#pragma unroll
        for (int k = 0; k < BK; k++) {
            const ulonglong2* ap = (const ulonglong2*)&Ab[k * ASTRIDE + ty * 16];
            const ulonglong2* wq = (const ulonglong2*)&Wb[k * BN + tx * 8];
            ulonglong2 A0 = ap[0], A1 = ap[1], A2 = ap[2], A3 = ap[3];
            ulonglong2 W0 = wq[0], W1 = wq[1];
            u64 av[8] = {A0.x, A0.y, A1.x, A1.y, A2.x, A2.y, A3.x, A3.y};
            u64 wv[4] = {W0.x, W0.y, W1.x, W1.y};
#pragma unroll
            for (int i = 0; i < 8; i++)
#pragma unroll
                for (int j = 0; j < 4; j++)
                    acc[i][j] = fma2(wv[j], av[i], acc[i][j]);
        }
        if (it < 15) {
            float* adst = cur ? adst0 : adst1;
            *(u64*)(adst + 0 * ASTRIDE) = pack2(nv.x, nv.x);
            *(u64*)(adst + 1 * ASTRIDE) = pack2(nv.y, nv.y);
            *(u64*)(adst + 2 * ASTRIDE) = pack2(nv.z, nv.z);
            *(u64*)(adst + 3 * ASTRIDE) = pack2(nv.w, nv.w);
            CPWAIT0();
            __syncthreads();
        }
    }

    // epilogue: store + shuffle-free partial attention dots
    int cbase = c0 + tx * 8;
    int h = cbase >> 6;
    const float4* as4 = (const float4*)&att_src[cbase];
    const float4* ad4 = (const float4*)&att_dst[cbase];
    float4 s0 = as4[0], s1 = as4[1];
    float4 d0 = ad4[0], d1 = ad4[1];

#pragma unroll
    for (int i = 0; i < 8; i++) {
        int node = n0 + ty * 8 + i;
        if (node >= N) break;
        float4 f0, f1;
        unpack2(acc[i][0], f0.x, f0.y);
        unpack2(acc[i][1], f0.z, f0.w);
        unpack2(acc[i][2], f1.x, f1.y);
        unpack2(acc[i][3], f1.z, f1.w);
        float* o = &g_h1[node * HC + cbase];
        *(float4*)(o + 0) = f0;
        *(float4*)(o + 4) = f1;
        float s = f0.x * s0.x + f0.y * s0.y + f0.z * s0.z + f0.w * s0.w
                + f1.x * s1.x + f1.y * s1.y + f1.z * s1.z + f1.w * s1.w;
        float d = f0.x * d0.x + f0.y * d0.y + f0.z * d0.z + f0.w * d0.w
                + f1.x * d1.x + f1.y * d1.y + f1.z * d1.z + f1.w * d1.w;
        atomicAdd(&g_as1[node * H1 + h], s);
        atomicAdd(&g_ad1[node * H1 + h], d);
    }
}

// ---- fused layer-1 softmax+aggregation+layer-2 projection -------------------
// One WARP per destination node, barrier-free.
__global__ void agg1_kernel(const float* __restrict__ b1,
                            const float* __restrict__ W2,
                            const float* __restrict__ att_src2,
                            const float* __restrict__ att_dst2, int N) {
    int gid  = blockIdx.x * blockDim.x + threadIdx.x;
    int n    = gid >> 5;
    int lane = gid & 31;
    if (n >= N) return;
    int start = g_rowstart[n];
    int deg   = g_cnt[n];
    int cbase = lane * 8;
    int h     = lane >> 3;
    float ad  = g_ad1[n * 4 + h];

    float4 A0 = make_float4(0.f, 0.f, 0.f, 0.f);
    float4 A1 = make_float4(0.f, 0.f, 0.f, 0.f);
    float den = 0.f;

    int e = 0;
    for (; e + 2 <= deg; e += 2) {
        int s0i = g_csr_src[start + e];
        int s1i = g_csr_src[start + e + 1];
        float a0 = g_as1[s0i * 4 + h];
        float a1 = g_as1[s1i * 4 + h];
        const float4* p0 = (const float4*)&g_h1[s0i * HC + cbase];
        const float4* p1 = (const float4*)&g_h1[s1i * HC + cbase];
        float4 v00 = p0[0], v01 = p0[1];
        float4 v10 = p1[0], v11 = p1[1];
        float x0 = __expf(lrelu(a0 + ad));
        float x1 = __expf(lrelu(a1 + ad));
        den += x0 + x1;
        A0.x += x0 * v00.x; A0.y += x0 * v00.y; A0.z += x0 * v00.z; A0.w += x0 * v00.w;
        A1.x += x0 * v01.x; A1.y += x0 * v01.y; A1.z += x0 * v01.z; A1.w += x0 * v01.w;
        A0.x += x1 * v10.x; A0.y += x1 * v10.y; A0.z += x1 * v10.z; A0.w += x1 * v10.w;
        A1.x += x1 * v11.x; A1.y += x1 * v11.y; A1.z += x1 * v11.z; A1.w += x1 * v11.w;
    }
    if (e < deg) {
        int s0i = g_csr_src[start + e];
        float a0 = g_as1[s0i * 4 + h];
        const float4* p0 = (const float4*)&g_h1[s0i * HC + cbase];
        float4 v00 = p0[0], v01 = p0[1];
        float x0 = __expf(lrelu(a0 + ad));
        den += x0;
        A0.x += x0 * v00.x; A0.y += x0 * v00.y; A0.z += x0 * v00.z; A0.w += x0 * v00.w;
        A1.x += x0 * v01.x; A1.y += x0 * v01.y; A1.z += x0 * v01.z; A1.w += x0 * v01.w;
    }

    float inv = 1.f / (den + 1e-16f);
    const float4* b4 = (const float4*)&b1[cbase];
    float4 bb0 = b4[0], bb1 = b4[1];
    float4 y0, y1;
    y0.x = fmaxf(A0.x * inv + bb0.x, 0.f);
    y0.y = fmaxf(A0.y * inv + bb0.y, 0.f);
    y0.z = fmaxf(A0.z * inv + bb0.z, 0.f);
    y0.w = fmaxf(A0.w * inv + bb0.w, 0.f);
    y1.x = fmaxf(A1.x * inv + bb1.x, 0.f);
    y1.y = fmaxf(A1.y * inv + bb1.y, 0.f);
    y1.z = fmaxf(A1.z * inv + bb1.z, 0.f);
    y1.w = fmaxf(A1.w * inv + bb1.w, 0.f);

    const float4* w0q = (const float4*)&W2[cbase];
    const float4* w1q = (const float4*)&W2[HC + cbase];
    float4 wa0 = w0q[0], wa1 = w0q[1];
    float4 wb0 = w1q[0], wb1 = w1q[1];
    float p0 = y0.x * wa0.x + y0.y * wa0.y + y0.z * wa0.z + y0.w * wa0.w
             + y1.x * wa1.x + y1.y * wa1.y + y1.z * wa1.z + y1.w * wa1.w;
    float p1 = y0.x * wb0.x + y0.y * wb0.y + y0.z * wb0.z + y0.w * wb0.w
             + y1.x * wb1.x + y1.y * wb1.y + y1.z * wb1.z + y1.w * wb1.w;
#pragma unroll
    for (int o = 16; o; o >>= 1) {
        p0 += __shfl_down_sync(0xFFFFFFFFu, p0, o);
        p1 += __shfl_down_sync(0xFFFFFFFFu, p1, o);
    }
    if (lane == 0) {
        g_h2[n * 2 + 0] = p0;
        g_h2[n * 2 + 1] = p1;
        g_as2[n] = p0 * att_src2[0] + p1 * att_src2[1];
        g_ad2[n] = p0 * att_dst2[0] + p1 * att_dst2[1];
    }
}

// ---------------- fused layer-2: one warp per destination node --------------
__global__ void agg2_kernel(const float* __restrict__ b2,
                            float* __restrict__ out, int N) {
    int gid  = blockIdx.x * blockDim.x + threadIdx.x;
    int n    = gid >> 5;
    int lane = gid & 31;
    if (n >= N) return;
    int start = g_rowstart[n];
    int deg   = g_cnt[n];
    float adv = g_ad2[n];

    float den = 0.f, a0 = 0.f, a1 = 0.f;
    for (int e = lane; e < deg; e += 32) {
        int s  = g_csr_src[start + e];
        float ex = __expf(lrelu(g_as2[s] + adv));
        den += ex;
        float2 hv = *(const float2*)&g_h2[s * 2];
        a0 += ex * hv.x;
        a1 += ex * hv.y;
    }
#pragma unroll
    for (int o = 16; o; o >>= 1) {
        den += __shfl_xor_sync(0xFFFFFFFFu, den, o);
        a0  += __shfl_xor_sync(0xFFFFFFFFu, a0, o);
        a1  += __shfl_xor_sync(0xFFFFFFFFu, a1, o);
    }
    if (lane == 0) {
        float inv = 1.f / (den + 1e-16f);
        out[n * 2 + 0] = a0 * inv + b2[0];
        out[n * 2 + 1] = a1 * inv + b2[1];
    }
}

// ---------------- launch ----------------
extern "C" void kernel_launch(void* const* d_in, const int* in_sizes, int n_in,
                              void* d_out, int out_size) {
    const float* x        = (const float*)d_in[0];
    const void*  ei       = d_in[1];
    const float* W1       = (const float*)d_in[2];
    const float* att_src1 = (const float*)d_in[3];
    const float* att_dst1 = (const float*)d_in[4];
    const float* b1       = (const float*)d_in[5];
    const float* W2       = (const float*)d_in[6];
    const float* att_src2 = (const float*)d_in[7];
    const float* att_dst2 = (const float*)d_in[8];
    const float* b2       = (const float*)d_in[9];

    int N  = in_sizes[0] / F_IN;
    int E  = in_sizes[1] / 2;
    int EA = E + N;

    const int B = 256;
    int gE = (EA + B - 1) / B;
    int nb = (N + SCB - 1) / SCB;

    // Side stream + events for forked capture (created once, host-side only).
    static cudaStream_t sB = 0;
    static cudaEvent_t  ev0 = 0, evB = 0;
    if (!sB) {
        cudaStreamCreateWithFlags(&sB, cudaStreamNonBlocking);
        cudaEventCreateWithFlags(&ev0, cudaEventDisableTiming);
        cudaEventCreateWithFlags(&evB, cudaEventDisableTiming);
    }

    // -------- main stream (0): edge-side prologue --------
    detect_kernel<<<1, 32>>>(ei, 2 * E, (long long)N);                     // [0]
    zerocnt_kernel<<<(N + B - 1) / B, B>>>(N);                             // [1]

    // -------- fork: branch A (wt + gemm) on sB --------
    cudaEventRecord(ev0, 0);
    cudaStreamWaitEvent(sB, ev0, 0);
    wtzero_kernel<<<(N * H1 + B - 1) / B, B, 0, sB>>>(W1, N);              // [2]
    dim3 gg((N + BM - 1) / BM, HC / BN);
    gemm1_kernel<<<gg, 256, 0, sB>>>(x, N, att_src1, att_dst1);            // [3] (profiled)
    cudaEventRecord(evB, sB);

    // -------- branch B: CSR build on stream 0 (overlaps gemm) --------
    edges_hist_kernel<<<(2 * E + N + B - 1) / B, B>>>(ei, E, N);           // [4]
    scan1_kernel<<<nb, SCB>>>(N);                                          // [5]
    scan2_kernel<<<1, 256>>>(nb);                                          // [6]
    scan3_kernel<<<(N + B - 1) / B, B>>>(N);                               // [7]
    scatter_kernel<<<gE, B>>>(EA);                                         // [8]

    // -------- join + aggregation --------
    cudaStreamWaitEvent(0, evB, 0);
    agg1_kernel<<<(N * 32 + B - 1) / B, B>>>(b1, W2, att_src2, att_dst2, N); // [9]
    agg2_kernel<<<(N * 32 + B - 1) / B, B>>>(b2, (float*)d_out, N);          // [10]
}

// round 9
// speedup vs baseline: 2.8939x; 1.4080x over previous
#include <cuda_runtime.h>
#include <cstdint>

// Problem constants (shapes fixed by setup_inputs)
#define NMAX   50000
#define EAMAX  850000     // E + N self loops
#define F_IN   128
#define HC     256        // heads*out_ch layer 1
#define H1     4
#define SCB    1024       // scan block size

// gemm tiling (tensor-core tf32)
#define BMt 128
#define BNt 128
#define KC  8             // k per chunk, 16 chunks
#define SPAD 136          // smem row stride (8 pad -> conflict-free frag access)

typedef unsigned long long u64;

// ---------------- scratch (static __device__, allocation-free) ----------------
__device__ float    g_h1[NMAX * HC];
__device__ uint32_t g_Wt[F_IN * HC];       // W1 transposed [k][c], tf32 bits
__device__ float    g_as1[NMAX * H1];
__device__ float    g_ad1[NMAX * H1];
__device__ int      g_src[EAMAX];
__device__ int      g_dst[EAMAX];
__device__ int      g_cnt[NMAX];
__device__ int      g_rowstart[NMAX];
__device__ int      g_fill[NMAX];
__device__ int      g_csr_src[EAMAX];
__device__ int      g_bsum[64];
__device__ int      g_boff[64];
__device__ float    g_h2[NMAX * 2];
__device__ float    g_as2[NMAX];
__device__ float    g_ad2[NMAX];
__device__ int      g_is64;

// ---------------- helpers ----------------
__device__ __forceinline__ float lrelu(float x) { return x > 0.f ? x : 0.2f * x; }

__device__ __forceinline__ uint32_t f2tf(float f) {
    uint32_t u;
    asm("cvt.rna.tf32.f32 %0, %1;" : "=r"(u) : "f"(f));
    return u;
}

__device__ __forceinline__ void mma16n8k8(float* d, const uint32_t* a,
                                          uint32_t b0, uint32_t b1) {
    asm volatile(
        "mma.sync.aligned.m16n8k8.row.col.f32.tf32.tf32.f32 "
        "{%0,%1,%2,%3}, {%4,%5,%6,%7}, {%8,%9}, {%0,%1,%2,%3};"
        : "+f"(d[0]), "+f"(d[1]), "+f"(d[2]), "+f"(d[3])
        : "r"(a[0]), "r"(a[1]), "r"(a[2]), "r"(a[3]), "r"(b0), "r"(b1));
}

// ---------------- setup kernels ----------------
__global__ void detect_kernel(const void* ei, int twoE, long long N) {
    int lane = threadIdx.x;
    const long long* p = (const long long*)ei;
    int m = twoE < 64 ? twoE : 64;
    int bad = 0;
#pragma unroll
    for (int r = 0; r < 2; r++) {
        int i = lane + 32 * r;
        if (i < m) {
            long long v = p[i];
            if (v < 0 || v >= N) bad = 1;
        }
    }
    unsigned anybad = __ballot_sync(0xFFFFFFFFu, bad);
    if (lane == 0) g_is64 = (anybad == 0u) ? 1 : 0;
}

__global__ void zerocnt_kernel(int N) {
    int i = blockIdx.x * blockDim.x + threadIdx.x;
    if (i < N) g_cnt[i] = 0;
}

// Wt transpose (fp32 -> tf32 bits) + zero as1/ad1
__global__ void wtzero_kernel(const float* __restrict__ W1, int N) {
    int i = blockIdx.x * blockDim.x + threadIdx.x;
    if (i < F_IN * HC) {
        int k = i / HC, c = i % HC;
        g_Wt[i] = f2tf(W1[c * F_IN + k]);
    }
    if (i < N * H1) { g_as1[i] = 0.f; g_ad1[i] = 0.f; }
}

// split edge_index + self loops + fused dst histogram
__global__ void edges_hist_kernel(const void* ei, int E, int N) {
    int i = blockIdx.x * blockDim.x + threadIdx.x;
    int twoE = 2 * E;
    if (i < twoE) {
        int v;
        if (g_is64) v = (int)((const long long*)ei)[i];
        else        v = ((const int*)ei)[i];
        if (i < E) g_src[i] = v;
        else {
            g_dst[i - E] = v;
            atomicAdd(&g_cnt[v], 1);
        }
    } else if (i < twoE + N) {
        int n = i - twoE;
        g_src[E + n] = n;
        g_dst[E + n] = n;
        atomicAdd(&g_cnt[n], 1);
    }
}

// hierarchical scan
__global__ void scan1_kernel(int N) {
    __shared__ int sp[SCB];
    int t = threadIdx.x;
    int i = blockIdx.x * SCB + t;
    int val = (i < N) ? g_cnt[i] : 0;
    sp[t] = val;
    __syncthreads();
    for (int off = 1; off < SCB; off <<= 1) {
        int v = (t >= off) ? sp[t - off] : 0;
        __syncthreads();
        sp[t] += v;
        __syncthreads();
    }
    if (i < N) g_rowstart[i] = sp[t] - val;
    if (t == SCB - 1) g_bsum[blockIdx.x] = sp[t];
}

__global__ void scan2_kernel(int nb) {
    __shared__ int sp[256];
    int t = threadIdx.x;
    int val = (t < nb) ? g_bsum[t] : 0;
    sp[t] = val;
    __syncthreads();
    for (int off = 1; off < 256; off <<= 1) {
        int v = (t >= off) ? sp[t - off] : 0;
        __syncthreads();
        sp[t] += v;
        __syncthreads();
    }
    if (t < nb) g_boff[t] = sp[t] - val;
}

__global__ void scan3_kernel(int N) {
    int i = blockIdx.x * blockDim.x + threadIdx.x;
    if (i < N) {
        int v = g_rowstart[i] + g_boff[i >> 10];
        g_rowstart[i] = v;
        g_fill[i]     = v;
    }
}

__global__ void scatter_kernel(int EA) {
    int e = blockIdx.x * blockDim.x + threadIdx.x;
    if (e >= EA) return;
    int d = g_dst[e];
    int pos = atomicAdd(&g_fill[d], 1);
    g_csr_src[pos] = g_src[e];
}

// ------------- h1 = x @ W1^T : tf32 tensor-core GEMM, 128x128 tile ----------
// 8 warps = 4(m) x 2(n); warp tile 32x64 = 2x8 m16n8k8 frags.
// A/W staged per 8-k chunk as tf32 in smem [k][136] (conflict-free), register
// double-buffered, one syncthreads per chunk.
__global__ void __launch_bounds__(256, 2) gemm1_kernel(const float* __restrict__ x, int N,
                                                       const float* __restrict__ att_src,
                                                       const float* __restrict__ att_dst) {
    __shared__ uint32_t As[2][KC][SPAD];
    __shared__ uint32_t Ws[2][KC][SPAD];
    int t    = threadIdx.x;
    int w    = t >> 5;
    int lane = t & 31;
    int wm   = w & 3;          // rows wm*32 .. +32
    int wn   = w >> 2;         // cols wn*64 .. +64
    int r    = lane >> 2;      // frag row group 0..7
    int kq   = lane & 3;       // frag k / col quad
    int n0   = blockIdx.x * BMt;
    int c0   = blockIdx.y * BNt;

    // staging assignment
    int nodeA = t & 127, kh = (t >> 7) * 4;           // A: 128 nodes x 2 k-halves
    bool aok = (n0 + nodeA) < N;
    const float* xrow = &x[(size_t)(n0 + nodeA) * F_IN];
    int kkW = t >> 5, cW = (t & 31) * 4;              // W: 8 k-rows x 32 col-quads
    const uint32_t* wsrc = &g_Wt[kkW * HC + c0 + cW];

    float acc[2][8][4];
#pragma unroll
    for (int mi = 0; mi < 2; mi++)
#pragma unroll
        for (int ni = 0; ni < 8; ni++)
#pragma unroll
            for (int j = 0; j < 4; j++) acc[mi][ni][j] = 0.f;

    float4 av = make_float4(0.f, 0.f, 0.f, 0.f);
    uint4  wv;
    // prologue: stage chunk 0 -> buffer 0
    if (aok) av = *(const float4*)&xrow[kh];
    wv = *(const uint4*)wsrc;
    As[0][kh + 0][nodeA] = f2tf(av.x);
    As[0][kh + 1][nodeA] = f2tf(av.y);
    As[0][kh + 2][nodeA] = f2tf(av.z);
    As[0][kh + 3][nodeA] = f2tf(av.w);
    *(uint4*)&Ws[0][kkW][cW] = wv;
    __syncthreads();

    for (int it = 0; it < 16; it++) {
        int cur = it & 1;
        if (it < 15) {
            int k0 = (it + 1) * KC;
            av = make_float4(0.f, 0.f, 0.f, 0.f);
            if (aok) av = *(const float4*)&xrow[k0 + kh];
            wv = *(const uint4*)(wsrc + k0 * HC);
        }
        // fragment loads + mma
        uint32_t a[2][4];
#pragma unroll
        for (int mi = 0; mi < 2; mi++) {
            int rb = wm * 32 + mi * 16 + r;
            a[mi][0] = As[cur][kq][rb];
            a[mi][1] = As[cur][kq][rb + 8];
            a[mi][2] = As[cur][kq + 4][rb];
            a[mi][3] = As[cur][kq + 4][rb + 8];
        }
#pragma unroll
        for (int ni = 0; ni < 8; ni++) {
            int cb = wn * 64 + ni * 8 + r;
            uint32_t b0 = Ws[cur][kq][cb];
            uint32_t b1 = Ws[cur][kq + 4][cb];
            mma16n8k8(acc[0][ni], a[0], b0, b1);
            mma16n8k8(acc[1][ni], a[1], b0, b1);
        }
        if (it < 15) {
            int nxt = cur ^ 1;
            As[nxt][kh + 0][nodeA] = f2tf(av.x);
            As[nxt][kh + 1][nodeA] = f2tf(av.y);
            As[nxt][kh + 2][nodeA] = f2tf(av.z);
            As[nxt][kh + 3][nodeA] = f2tf(av.w);
            *(uint4*)&Ws[nxt][kkW][cW] = wv;
            __syncthreads();
        }
    }

    // epilogue: store h1 + partial attention dots (one head per warp)
    int hbase = (c0 + wn * 64) >> 6;
    float sA[2][2] = {{0.f, 0.f}, {0.f, 0.f}};   // [mi][lo/hi]
    float dA[2][2] = {{0.f, 0.f}, {0.f, 0.f}};
#pragma unroll
    for (int mi = 0; mi < 2; mi++) {
        int row_lo = n0 + wm * 32 + mi * 16 + r;
        int row_hi = row_lo + 8;
#pragma unroll
        for (int ni = 0; ni < 8; ni++) {
            const float* dd = acc[mi][ni];
            int col = c0 + wn * 64 + ni * 8 + 2 * kq;
            if (row_lo < N) *(float2*)&g_h1[(size_t)row_lo * HC + col] = make_float2(dd[0], dd[1]);
            if (row_hi < N) *(float2*)&g_h1[(size_t)row_hi * HC + col] = make_float2(dd[2], dd[3]);
            float2 as = *(const float2*)&att_src[col];
            float2 ad = *(const float2*)&att_dst[col];
            sA[mi][0] += dd[0] * as.x + dd[1] * as.y;
            sA[mi][1] += dd[2] * as.x + dd[3] * as.y;
            dA[mi][0] += dd[0] * ad.x + dd[1] * ad.y;
            dA[mi][1] += dd[2] * ad.x + dd[3] * ad.y;
        }
    }
#pragma unroll
    for (int mi = 0; mi < 2; mi++)
#pragma unroll
        for (int j = 0; j < 2; j++) {
            sA[mi][j] += __shfl_down_sync(0xFFFFFFFFu, sA[mi][j], 2, 4);
            sA[mi][j] += __shfl_down_sync(0xFFFFFFFFu, sA[mi][j], 1, 4);
            dA[mi][j] += __shfl_down_sync(0xFFFFFFFFu, dA[mi][j], 2, 4);
            dA[mi][j] += __shfl_down_sync(0xFFFFFFFFu, dA[mi][j], 1, 4);
        }
    if (kq == 0) {
#pragma unroll
        for (int mi = 0; mi < 2; mi++)
#pragma unroll
            for (int j = 0; j < 2; j++) {
                int node = n0 + wm * 32 + mi * 16 + j * 8 + r;
                if (node < N) {
                    atomicAdd(&g_as1[node * H1 + hbase], sA[mi][j]);
                    atomicAdd(&g_ad1[node * H1 + hbase], dA[mi][j]);
                }
            }
    }
}

// ---- fused layer-1 softmax+aggregation+layer-2 projection -------------------
// One WARP per destination node, barrier-free.
__global__ void agg1_kernel(const float* __restrict__ b1,
                            const float* __restrict__ W2,
                            const float* __restrict__ att_src2,
                            const float* __restrict__ att_dst2, int N) {
    int gid  = blockIdx.x * blockDim.x + threadIdx.x;
    int n    = gid >> 5;
    int lane = gid & 31;
    if (n >= N) return;
    int start = g_rowstart[n];
    int deg   = g_cnt[n];
    int cbase = lane * 8;
    int h     = lane >> 3;
    float ad  = g_ad1[n * 4 + h];

    float4 A0 = make_float4(0.f, 0.f, 0.f, 0.f);
    float4 A1 = make_float4(0.f, 0.f, 0.f, 0.f);
    float den = 0.f;

    int e = 0;
    for (; e + 2 <= deg; e += 2) {
        int s0i = g_csr_src[start + e];
        int s1i = g_csr_src[start + e + 1];
        float a0 = g_as1[s0i * 4 + h];
        float a1 = g_as1[s1i * 4 + h];
        const float4* p0 = (const float4*)&g_h1[s0i * HC + cbase];
        const float4* p1 = (const float4*)&g_h1[s1i * HC + cbase];
        float4 v00 = p0[0], v01 = p0[1];
        float4 v10 = p1[0], v11 = p1[1];
        float x0 = __expf(lrelu(a0 + ad));
        float x1 = __expf(lrelu(a1 + ad));
        den += x0 + x1;
        A0.x += x0 * v00.x; A0.y += x0 * v00.y; A0.z += x0 * v00.z; A0.w += x0 * v00.w;
        A1.x += x0 * v01.x; A1.y += x0 * v01.y; A1.z += x0 * v01.z; A1.w += x0 * v01.w;
        A0.x += x1 * v10.x; A0.y += x1 * v10.y; A0.z += x1 * v10.z; A0.w += x1 * v10.w;
        A1.x += x1 * v11.x; A1.y += x1 * v11.y; A1.z += x1 * v11.z; A1.w += x1 * v11.w;
    }
    if (e < deg) {
        int s0i = g_csr_src[start + e];
        float a0 = g_as1[s0i * 4 + h];
        const float4* p0 = (const float4*)&g_h1[s0i * HC + cbase];
        float4 v00 = p0[0], v01 = p0[1];
        float x0 = __expf(lrelu(a0 + ad));
        den += x0;
        A0.x += x0 * v00.x; A0.y += x0 * v00.y; A0.z += x0 * v00.z; A0.w += x0 * v00.w;
        A1.x += x0 * v01.x; A1.y += x0 * v01.y; A1.z += x0 * v01.z; A1.w += x0 * v01.w;
    }

    float inv = 1.f / (den + 1e-16f);
    const float4* b4 = (const float4*)&b1[cbase];
    float4 bb0 = b4[0], bb1 = b4[1];
    float4 y0, y1;
    y0.x = fmaxf(A0.x * inv + bb0.x, 0.f);
    y0.y = fmaxf(A0.y * inv + bb0.y, 0.f);
    y0.z = fmaxf(A0.z * inv + bb0.z, 0.f);
    y0.w = fmaxf(A0.w * inv + bb0.w, 0.f);
    y1.x = fmaxf(A1.x * inv + bb1.x, 0.f);
    y1.y = fmaxf(A1.y * inv + bb1.y, 0.f);
    y1.z = fmaxf(A1.z * inv + bb1.z, 0.f);
    y1.w = fmaxf(A1.w * inv + bb1.w, 0.f);

    const float4* w0q = (const float4*)&W2[cbase];
    const float4* w1q = (const float4*)&W2[HC + cbase];
    float4 wa0 = w0q[0], wa1 = w0q[1];
    float4 wb0 = w1q[0], wb1 = w1q[1];
    float p0 = y0.x * wa0.x + y0.y * wa0.y + y0.z * wa0.z + y0.w * wa0.w
             + y1.x * wa1.x + y1.y * wa1.y + y1.z * wa1.z + y1.w * wa1.w;
    float p1 = y0.x * wb0.x + y0.y * wb0.y + y0.z * wb0.z + y0.w * wb0.w
             + y1.x * wb1.x + y1.y * wb1.y + y1.z * wb1.z + y1.w * wb1.w;
#pragma unroll
    for (int o = 16; o; o >>= 1) {
        p0 += __shfl_down_sync(0xFFFFFFFFu, p0, o);
        p1 += __shfl_down_sync(0xFFFFFFFFu, p1, o);
    }
    if (lane == 0) {
        g_h2[n * 2 + 0] = p0;
        g_h2[n * 2 + 1] = p1;
        g_as2[n] = p0 * att_src2[0] + p1 * att_src2[1];
        g_ad2[n] = p0 * att_dst2[0] + p1 * att_dst2[1];
    }
}

// ---------------- fused layer-2: one warp per destination node --------------
__global__ void agg2_kernel(const float* __restrict__ b2,
                            float* __restrict__ out, int N) {
    int gid  = blockIdx.x * blockDim.x + threadIdx.x;
    int n    = gid >> 5;
    int lane = gid & 31;
    if (n >= N) return;
    int start = g_rowstart[n];
    int deg   = g_cnt[n];
    float adv = g_ad2[n];

    float den = 0.f, a0 = 0.f, a1 = 0.f;
    for (int e = lane; e < deg; e += 32) {
        int s  = g_csr_src[start + e];
        float ex = __expf(lrelu(g_as2[s] + adv));
        den += ex;
        float2 hv = *(const float2*)&g_h2[s * 2];
        a0 += ex * hv.x;
        a1 += ex * hv.y;
    }
#pragma unroll
    for (int o = 16; o; o >>= 1) {
        den += __shfl_xor_sync(0xFFFFFFFFu, den, o);
        a0  += __shfl_xor_sync(0xFFFFFFFFu, a0, o);
        a1  += __shfl_xor_sync(0xFFFFFFFFu, a1, o);
    }
    if (lane == 0) {
        float inv = 1.f / (den + 1e-16f);
        out[n * 2 + 0] = a0 * inv + b2[0];
        out[n * 2 + 1] = a1 * inv + b2[1];
    }
}

// ---------------- launch ----------------
extern "C" void kernel_launch(void* const* d_in, const int* in_sizes, int n_in,
                              void* d_out, int out_size) {
    const float* x        = (const float*)d_in[0];
    const void*  ei       = d_in[1];
    const float* W1       = (const float*)d_in[2];
    const float* att_src1 = (const float*)d_in[3];
    const float* att_dst1 = (const float*)d_in[4];
    const float* b1       = (const float*)d_in[5];
    const float* W2       = (const float*)d_in[6];
    const float* att_src2 = (const float*)d_in[7];
    const float* att_dst2 = (const float*)d_in[8];
    const float* b2       = (const float*)d_in[9];

    int N  = in_sizes[0] / F_IN;
    int E  = in_sizes[1] / 2;
    int EA = E + N;

    const int B = 256;
    int gE = (EA + B - 1) / B;
    int nb = (N + SCB - 1) / SCB;

    // Side stream + events for forked capture (created once, host-side only).
    static cudaStream_t sB = 0;
    static cudaEvent_t  ev0 = 0, evB = 0;
    if (!sB) {
        cudaStreamCreateWithFlags(&sB, cudaStreamNonBlocking);
        cudaEventCreateWithFlags(&ev0, cudaEventDisableTiming);
        cudaEventCreateWithFlags(&evB, cudaEventDisableTiming);
    }

    // -------- main stream (0): edge-side prologue --------
    detect_kernel<<<1, 32>>>(ei, 2 * E, (long long)N);                     // [0]
    zerocnt_kernel<<<(N + B - 1) / B, B>>>(N);                             // [1]

    // -------- fork: branch A (wt + gemm) on sB --------
    cudaEventRecord(ev0, 0);
    cudaStreamWaitEvent(sB, ev0, 0);
    wtzero_kernel<<<(N * H1 + B - 1) / B, B, 0, sB>>>(W1, N);              // [2]
    dim3 gg((N + BMt - 1) / BMt, HC / BNt);
    gemm1_kernel<<<gg, 256, 0, sB>>>(x, N, att_src1, att_dst1);            // [3] (profiled)
    cudaEventRecord(evB, sB);

    // -------- branch B: CSR build on stream 0 (overlaps gemm) --------
    edges_hist_kernel<<<(2 * E + N + B - 1) / B, B>>>(ei, E, N);           // [4]
    scan1_kernel<<<nb, SCB>>>(N);                                          // [5]
    scan2_kernel<<<1, 256>>>(nb);                                          // [6]
    scan3_kernel<<<(N + B - 1) / B, B>>>(N);                               // [7]
    scatter_kernel<<<gE, B>>>(EA);                                         // [8]

    // -------- join + aggregation --------
    cudaStreamWaitEvent(0, evB, 0);
    agg1_kernel<<<(N * 32 + B - 1) / B, B>>>(b1, W2, att_src2, att_dst2, N); // [9]
    agg2_kernel<<<(N * 32 + B - 1) / B, B>>>(b2, (float*)d_out, N);          // [10]
}

// round 10
// speedup vs baseline: 3.5175x; 1.2155x over previous
#include <cuda_runtime.h>
#include <cuda_fp16.h>
#include <cstdint>

// Problem constants (shapes fixed by setup_inputs)
#define NMAX   50000
#define EAMAX  850000     // E + N self loops
#define F_IN   128
#define HC     256        // heads*out_ch layer 1
#define H1     4
#define SCB    1024       // scan block size

// gemm tiling (tensor-core tf32)
#define BMt 128
#define BNt 128
#define KC  8             // k per chunk, 16 chunks
#define SPAD 136          // smem row stride (8 pad -> conflict-free frag access)

typedef unsigned long long u64;

// ---------------- scratch (static __device__, allocation-free) ----------------
__device__ __half   g_h1h[NMAX * HC];      // layer-1 features, fp16 (gather traffic /2)
__device__ uint32_t g_Wt[F_IN * HC];       // W1 transposed [k][c], tf32 bits
__device__ float    g_as1[NMAX * H1];
__device__ float    g_ad1[NMAX * H1];
__device__ int      g_src[EAMAX];
__device__ int      g_dst[EAMAX];
__device__ int      g_cnt[NMAX];
__device__ int      g_rowstart[NMAX];
__device__ int      g_fill[NMAX];
__device__ int      g_csr_src[EAMAX];
__device__ int      g_bsum[64];
__device__ int      g_boff[64];
__device__ float    g_h2[NMAX * 2];
__device__ float    g_as2[NMAX];
__device__ float    g_ad2[NMAX];
__device__ int      g_is64;

// ---------------- helpers ----------------
__device__ __forceinline__ float lrelu(float x) { return x > 0.f ? x : 0.2f * x; }

__device__ __forceinline__ uint32_t f2tf(float f) {
    uint32_t u;
    asm("cvt.rna.tf32.f32 %0, %1;" : "=r"(u) : "f"(f));
    return u;
}

__device__ __forceinline__ void mma16n8k8(float* d, const uint32_t* a,
                                          uint32_t b0, uint32_t b1) {
    asm volatile(
        "mma.sync.aligned.m16n8k8.row.col.f32.tf32.tf32.f32 "
        "{%0,%1,%2,%3}, {%4,%5,%6,%7}, {%8,%9}, {%0,%1,%2,%3};"
        : "+f"(d[0]), "+f"(d[1]), "+f"(d[2]), "+f"(d[3])
        : "r"(a[0]), "r"(a[1]), "r"(a[2]), "r"(a[3]), "r"(b0), "r"(b1));
}

// ---------------- setup kernels ----------------
__global__ void detect_kernel(const void* ei, int twoE, long long N) {
    int lane = threadIdx.x;
    const long long* p = (const long long*)ei;
    int m = twoE < 64 ? twoE : 64;
    int bad = 0;
#pragma unroll
    for (int r = 0; r < 2; r++) {
        int i = lane + 32 * r;
        if (i < m) {
            long long v = p[i];
            if (v < 0 || v >= N) bad = 1;
        }
    }
    unsigned anybad = __ballot_sync(0xFFFFFFFFu, bad);
    if (lane == 0) g_is64 = (anybad == 0u) ? 1 : 0;
}

__global__ void zerocnt_kernel(int N) {
    int i = blockIdx.x * blockDim.x + threadIdx.x;
    if (i < N) g_cnt[i] = 0;
}

// Wt transpose (fp32 -> tf32 bits) + zero as1/ad1
__global__ void wtzero_kernel(const float* __restrict__ W1, int N) {
    int i = blockIdx.x * blockDim.x + threadIdx.x;
    if (i < F_IN * HC) {
        int k = i / HC, c = i % HC;
        g_Wt[i] = f2tf(W1[c * F_IN + k]);
    }
    if (i < N * H1) { g_as1[i] = 0.f; g_ad1[i] = 0.f; }
}

// split edge_index + self loops + fused dst histogram
__global__ void edges_hist_kernel(const void* ei, int E, int N) {
    int i = blockIdx.x * blockDim.x + threadIdx.x;
    int twoE = 2 * E;
    if (i < twoE) {
        int v;
        if (g_is64) v = (int)((const long long*)ei)[i];
        else        v = ((const int*)ei)[i];
        if (i < E) g_src[i] = v;
        else {
            g_dst[i - E] = v;
            atomicAdd(&g_cnt[v], 1);
        }
    } else if (i < twoE + N) {
        int n = i - twoE;
        g_src[E + n] = n;
        g_dst[E + n] = n;
        atomicAdd(&g_cnt[n], 1);
    }
}

// hierarchical scan
__global__ void scan1_kernel(int N) {
    __shared__ int sp[SCB];
    int t = threadIdx.x;
    int i = blockIdx.x * SCB + t;
    int val = (i < N) ? g_cnt[i] : 0;
    sp[t] = val;
    __syncthreads();
    for (int off = 1; off < SCB; off <<= 1) {
        int v = (t >= off) ? sp[t - off] : 0;
        __syncthreads();
        sp[t] += v;
        __syncthreads();
    }
    if (i < N) g_rowstart[i] = sp[t] - val;
    if (t == SCB - 1) g_bsum[blockIdx.x] = sp[t];
}

__global__ void scan2_kernel(int nb) {
    __shared__ int sp[256];
    int t = threadIdx.x;
    int val = (t < nb) ? g_bsum[t] : 0;
    sp[t] = val;
    __syncthreads();
    for (int off = 1; off < 256; off <<= 1) {
        int v = (t >= off) ? sp[t - off] : 0;
        __syncthreads();
        sp[t] += v;
        __syncthreads();
    }
    if (t < nb) g_boff[t] = sp[t] - val;
}

__global__ void scan3_kernel(int N) {
    int i = blockIdx.x * blockDim.x + threadIdx.x;
    if (i < N) {
        int v = g_rowstart[i] + g_boff[i >> 10];
        g_rowstart[i] = v;
        g_fill[i]     = v;
    }
}

__global__ void scatter_kernel(int EA) {
    int e = blockIdx.x * blockDim.x + threadIdx.x;
    if (e >= EA) return;
    int d = g_dst[e];
    int pos = atomicAdd(&g_fill[d], 1);
    g_csr_src[pos] = g_src[e];
}

// ------------- h1 = x @ W1^T : tf32 tensor-core GEMM, fp16 h1 output --------
__global__ void __launch_bounds__(256, 2) gemm1_kernel(const float* __restrict__ x, int N,
                                                       const float* __restrict__ att_src,
                                                       const float* __restrict__ att_dst) {
    __shared__ uint32_t As[2][KC][SPAD];
    __shared__ uint32_t Ws[2][KC][SPAD];
    int t    = threadIdx.x;
    int w    = t >> 5;
    int lane = t & 31;
    int wm   = w & 3;          // rows wm*32 .. +32
    int wn   = w >> 2;         // cols wn*64 .. +64
    int r    = lane >> 2;      // frag row group 0..7
    int kq   = lane & 3;       // frag k / col quad
    int n0   = blockIdx.x * BMt;
    int c0   = blockIdx.y * BNt;

    // staging assignment
    int nodeA = t & 127, kh = (t >> 7) * 4;           // A: 128 nodes x 2 k-halves
    bool aok = (n0 + nodeA) < N;
    const float* xrow = &x[(size_t)(n0 + nodeA) * F_IN];
    int kkW = t >> 5, cW = (t & 31) * 4;              // W: 8 k-rows x 32 col-quads
    const uint32_t* wsrc = &g_Wt[kkW * HC + c0 + cW];

    float acc[2][8][4];
#pragma unroll
    for (int mi = 0; mi < 2; mi++)
#pragma unroll
        for (int ni = 0; ni < 8; ni++)
#pragma unroll
            for (int j = 0; j < 4; j++) acc[mi][ni][j] = 0.f;

    float4 av = make_float4(0.f, 0.f, 0.f, 0.f);
    uint4  wv;
    // prologue: stage chunk 0 -> buffer 0
    if (aok) av = *(const float4*)&xrow[kh];
    wv = *(const uint4*)wsrc;
    As[0][kh + 0][nodeA] = f2tf(av.x);
    As[0][kh + 1][nodeA] = f2tf(av.y);
    As[0][kh + 2][nodeA] = f2tf(av.z);
    As[0][kh + 3][nodeA] = f2tf(av.w);
    *(uint4*)&Ws[0][kkW][cW] = wv;
    __syncthreads();

    for (int it = 0; it < 16; it++) {
        int cur = it & 1;
        if (it < 15) {
            int k0 = (it + 1) * KC;
            av = make_float4(0.f, 0.f, 0.f, 0.f);
            if (aok) av = *(const float4*)&xrow[k0 + kh];
            wv = *(const uint4*)(wsrc + k0 * HC);
        }
        uint32_t a[2][4];
#pragma unroll
        for (int mi = 0; mi < 2; mi++) {
            int rb = wm * 32 + mi * 16 + r;
            a[mi][0] = As[cur][kq][rb];
            a[mi][1] = As[cur][kq][rb + 8];
            a[mi][2] = As[cur][kq + 4][rb];
            a[mi][3] = As[cur][kq + 4][rb + 8];
        }
#pragma unroll
        for (int ni = 0; ni < 8; ni++) {
            int cb = wn * 64 + ni * 8 + r;
            uint32_t b0 = Ws[cur][kq][cb];
            uint32_t b1 = Ws[cur][kq + 4][cb];
            mma16n8k8(acc[0][ni], a[0], b0, b1);
            mma16n8k8(acc[1][ni], a[1], b0, b1);
        }
        if (it < 15) {
            int nxt = cur ^ 1;
            As[nxt][kh + 0][nodeA] = f2tf(av.x);
            As[nxt][kh + 1][nodeA] = f2tf(av.y);
            As[nxt][kh + 2][nodeA] = f2tf(av.z);
            As[nxt][kh + 3][nodeA] = f2tf(av.w);
            *(uint4*)&Ws[nxt][kkW][cW] = wv;
            __syncthreads();
        }
    }

    // epilogue: store h1 (fp16) + partial attention dots (one head per warp)
    int hbase = (c0 + wn * 64) >> 6;
    float sA[2][2] = {{0.f, 0.f}, {0.f, 0.f}};
    float dA[2][2] = {{0.f, 0.f}, {0.f, 0.f}};
#pragma unroll
    for (int mi = 0; mi < 2; mi++) {
        int row_lo = n0 + wm * 32 + mi * 16 + r;
        int row_hi = row_lo + 8;
#pragma unroll
        for (int ni = 0; ni < 8; ni++) {
            const float* dd = acc[mi][ni];
            int col = c0 + wn * 64 + ni * 8 + 2 * kq;
            if (row_lo < N)
                *(__half2*)&g_h1h[(size_t)row_lo * HC + col] =
                    __float22half2_rn(make_float2(dd[0], dd[1]));
            if (row_hi < N)
                *(__half2*)&g_h1h[(size_t)row_hi * HC + col] =
                    __float22half2_rn(make_float2(dd[2], dd[3]));
            float2 as = *(const float2*)&att_src[col];
            float2 ad = *(const float2*)&att_dst[col];
            sA[mi][0] += dd[0] * as.x + dd[1] * as.y;
            sA[mi][1] += dd[2] * as.x + dd[3] * as.y;
            dA[mi][0] += dd[0] * ad.x + dd[1] * ad.y;
            dA[mi][1] += dd[2] * ad.x + dd[3] * ad.y;
        }
    }
#pragma unroll
    for (int mi = 0; mi < 2; mi++)
#pragma unroll
        for (int j = 0; j < 2; j++) {
            sA[mi][j] += __shfl_down_sync(0xFFFFFFFFu, sA[mi][j], 2, 4);
            sA[mi][j] += __shfl_down_sync(0xFFFFFFFFu, sA[mi][j], 1, 4);
            dA[mi][j] += __shfl_down_sync(0xFFFFFFFFu, dA[mi][j], 2, 4);
            dA[mi][j] += __shfl_down_sync(0xFFFFFFFFu, dA[mi][j], 1, 4);
        }
    if (kq == 0) {
#pragma unroll
        for (int mi = 0; mi < 2; mi++)
#pragma unroll
            for (int j = 0; j < 2; j++) {
                int node = n0 + wm * 32 + mi * 16 + j * 8 + r;
                if (node < N) {
                    atomicAdd(&g_as1[node * H1 + hbase], sA[mi][j]);
                    atomicAdd(&g_ad1[node * H1 + hbase], dA[mi][j]);
                }
            }
    }
}

// ---- fused layer-1 softmax+aggregation+layer-2 projection -------------------
// One WARP per destination node; fp16 gather (16B/lane/edge), 4-edge unroll.
__global__ void agg1_kernel(const float* __restrict__ b1,
                            const float* __restrict__ W2,
                            const float* __restrict__ att_src2,
                            const float* __restrict__ att_dst2, int N) {
    int gid  = blockIdx.x * blockDim.x + threadIdx.x;
    int n    = gid >> 5;
    int lane = gid & 31;
    if (n >= N) return;
    int start = g_rowstart[n];
    int deg   = g_cnt[n];
    int cbase = lane * 8;
    int h     = lane >> 3;
    float ad  = g_ad1[n * 4 + h];

    float A[8];
#pragma unroll
    for (int j = 0; j < 8; j++) A[j] = 0.f;
    float den = 0.f;

    int e = 0;
    for (; e + 4 <= deg; e += 4) {
        int s0 = g_csr_src[start + e + 0];
        int s1 = g_csr_src[start + e + 1];
        int s2 = g_csr_src[start + e + 2];
        int s3 = g_csr_src[start + e + 3];
        float a0 = g_as1[s0 * 4 + h];
        float a1 = g_as1[s1 * 4 + h];
        float a2 = g_as1[s2 * 4 + h];
        float a3 = g_as1[s3 * 4 + h];
        uint4 v0 = *(const uint4*)&g_h1h[(size_t)s0 * HC + cbase];
        uint4 v1 = *(const uint4*)&g_h1h[(size_t)s1 * HC + cbase];
        uint4 v2 = *(const uint4*)&g_h1h[(size_t)s2 * HC + cbase];
        uint4 v3 = *(const uint4*)&g_h1h[(size_t)s3 * HC + cbase];
        float x0 = __expf(lrelu(a0 + ad));
        float x1 = __expf(lrelu(a1 + ad));
        float x2 = __expf(lrelu(a2 + ad));
        float x3 = __expf(lrelu(a3 + ad));
        den += (x0 + x1) + (x2 + x3);
        const uint32_t* vv[4] = {&v0.x, &v1.x, &v2.x, &v3.x};
        float xs[4] = {x0, x1, x2, x3};
#pragma unroll
        for (int q = 0; q < 4; q++) {
            float xq = xs[q];
#pragma unroll
            for (int j = 0; j < 4; j++) {
                float2 f = __half22float2(*(const __half2*)&vv[q][j]);
                A[2 * j + 0] += xq * f.x;
                A[2 * j + 1] += xq * f.y;
            }
        }
    }
    for (; e < deg; e++) {
        int s0 = g_csr_src[start + e];
        float a0 = g_as1[s0 * 4 + h];
        uint4 v0 = *(const uint4*)&g_h1h[(size_t)s0 * HC + cbase];
        float x0 = __expf(lrelu(a0 + ad));
        den += x0;
        const uint32_t* vv = &v0.x;
#pragma unroll
        for (int j = 0; j < 4; j++) {
            float2 f = __half22float2(*(const __half2*)&vv[j]);
            A[2 * j + 0] += x0 * f.x;
            A[2 * j + 1] += x0 * f.y;
        }
    }

    float inv = 1.f / (den + 1e-16f);
    const float4* b4 = (const float4*)&b1[cbase];
    float4 bb0 = b4[0], bb1 = b4[1];
    float y[8];
    y[0] = fmaxf(A[0] * inv + bb0.x, 0.f);
    y[1] = fmaxf(A[1] * inv + bb0.y, 0.f);
    y[2] = fmaxf(A[2] * inv + bb0.z, 0.f);
    y[3] = fmaxf(A[3] * inv + bb0.w, 0.f);
    y[4] = fmaxf(A[4] * inv + bb1.x, 0.f);
    y[5] = fmaxf(A[5] * inv + bb1.y, 0.f);
    y[6] = fmaxf(A[6] * inv + bb1.z, 0.f);
    y[7] = fmaxf(A[7] * inv + bb1.w, 0.f);

    const float4* w0q = (const float4*)&W2[cbase];
    const float4* w1q = (const float4*)&W2[HC + cbase];
    float4 wa0 = w0q[0], wa1 = w0q[1];
    float4 wb0 = w1q[0], wb1 = w1q[1];
    float p0 = y[0] * wa0.x + y[1] * wa0.y + y[2] * wa0.z + y[3] * wa0.w
             + y[4] * wa1.x + y[5] * wa1.y + y[6] * wa1.z + y[7] * wa1.w;
    float p1 = y[0] * wb0.x + y[1] * wb0.y + y[2] * wb0.z + y[3] * wb0.w
             + y[4] * wb1.x + y[5] * wb1.y + y[6] * wb1.z + y[7] * wb1.w;
#pragma unroll
    for (int o = 16; o; o >>= 1) {
        p0 += __shfl_down_sync(0xFFFFFFFFu, p0, o);
        p1 += __shfl_down_sync(0xFFFFFFFFu, p1, o);
    }
    if (lane == 0) {
        g_h2[n * 2 + 0] = p0;
        g_h2[n * 2 + 1] = p1;
        g_as2[n] = p0 * att_src2[0] + p1 * att_src2[1];
        g_ad2[n] = p0 * att_dst2[0] + p1 * att_dst2[1];
    }
}

// ---------------- fused layer-2: one warp per destination node --------------
__global__ void agg2_kernel(const float* __restrict__ b2,
                            float* __restrict__ out, int N) {
    int gid  = blockIdx.x * blockDim.x + threadIdx.x;
    int n    = gid >> 5;
    int lane = gid & 31;
    if (n >= N) return;
    int start = g_rowstart[n];
    int deg   = g_cnt[n];
    float adv = g_ad2[n];

    float den = 0.f, a0 = 0.f, a1 = 0.f;
    for (int e = lane; e < deg; e += 32) {
        int s  = g_csr_src[start + e];
        float ex = __expf(lrelu(g_as2[s] + adv));
        den += ex;
        float2 hv = *(const float2*)&g_h2[s * 2];
        a0 += ex * hv.x;
        a1 += ex * hv.y;
    }
#pragma unroll
    for (int o = 16; o; o >>= 1) {
        den += __shfl_xor_sync(0xFFFFFFFFu, den, o);
        a0  += __shfl_xor_sync(0xFFFFFFFFu, a0, o);
        a1  += __shfl_xor_sync(0xFFFFFFFFu, a1, o);
    }
    if (lane == 0) {
        float inv = 1.f / (den + 1e-16f);
        out[n * 2 + 0] = a0 * inv + b2[0];
        out[n * 2 + 1] = a1 * inv + b2[1];
    }
}

// ---------------- launch ----------------
extern "C" void kernel_launch(void* const* d_in, const int* in_sizes, int n_in,
                              void* d_out, int out_size) {
    const float* x        = (const float*)d_in[0];
    const void*  ei       = d_in[1];
    const float* W1       = (const float*)d_in[2];
    const float* att_src1 = (const float*)d_in[3];
    const float* att_dst1 = (const float*)d_in[4];
    const float* b1       = (const float*)d_in[5];
    const float* W2       = (const float*)d_in[6];
    const float* att_src2 = (const float*)d_in[7];
    const float* att_dst2 = (const float*)d_in[8];
    const float* b2       = (const float*)d_in[9];

    int N  = in_sizes[0] / F_IN;
    int E  = in_sizes[1] / 2;
    int EA = E + N;

    const int B = 256;
    int gE = (EA + B - 1) / B;
    int nb = (N + SCB - 1) / SCB;

    // Side stream + events for forked capture (created once, host-side only).
    static cudaStream_t sB = 0;
    static cudaEvent_t  ev0 = 0, evB = 0;
    if (!sB) {
        cudaStreamCreateWithFlags(&sB, cudaStreamNonBlocking);
        cudaEventCreateWithFlags(&ev0, cudaEventDisableTiming);
        cudaEventCreateWithFlags(&evB, cudaEventDisableTiming);
    }

    // -------- main stream (0): edge-side prologue --------
    detect_kernel<<<1, 32>>>(ei, 2 * E, (long long)N);                     // [0]
    zerocnt_kernel<<<(N + B - 1) / B, B>>>(N);                             // [1]

    // -------- fork: branch A (wt + gemm) on sB --------
    cudaEventRecord(ev0, 0);
    cudaStreamWaitEvent(sB, ev0, 0);
    wtzero_kernel<<<(N * H1 + B - 1) / B, B, 0, sB>>>(W1, N);              // [2]
    dim3 gg((N + BMt - 1) / BMt, HC / BNt);
    gemm1_kernel<<<gg, 256, 0, sB>>>(x, N, att_src1, att_dst1);            // [3] (profiled)
    cudaEventRecord(evB, sB);

    // -------- branch B: CSR build on stream 0 (overlaps gemm) --------
    edges_hist_kernel<<<(2 * E + N + B - 1) / B, B>>>(ei, E, N);           // [4]
    scan1_kernel<<<nb, SCB>>>(N);                                          // [5]
    scan2_kernel<<<1, 256>>>(nb);                                          // [6]
    scan3_kernel<<<(N + B - 1) / B, B>>>(N);                               // [7]
    scatter_kernel<<<gE, B>>>(EA);                                         // [8]

    // -------- join + aggregation --------
    cudaStreamWaitEvent(0, evB, 0);
    agg1_kernel<<<(N * 32 + B - 1) / B, B>>>(b1, W2, att_src2, att_dst2, N); // [9]
    agg2_kernel<<<(N * 32 + B - 1) / B, B>>>(b2, (float*)d_out, N);          // [10]
}

// round 12
// speedup vs baseline: 3.7787x; 1.0742x over previous
#include <cuda_runtime.h>
#include <cuda_fp16.h>
#include <cstdint>

// Problem constants (shapes fixed by setup_inputs)
#define NMAX   50000
#define EAMAX  850000     // E + N self loops
#define F_IN   128
#define HC     256        // heads*out_ch layer 1
#define H1     4
#define SCB    1024       // scan block size

// gemm tiling (fp16 HMMA)
#define BMt 128
#define BNt 128
#define KC  16            // k per chunk, 8 chunks
#define AST 24            // A smem stride in halves (48B: 16B-aligned, LDSM conflict-free)
#define WST 136           // W smem stride in halves (272B: 16B-aligned)

typedef unsigned long long u64;

// ---------------- scratch (static __device__, allocation-free) ----------------
__device__ __half   g_h1h[NMAX * HC];      // layer-1 features, fp16
__device__ __half   g_Wth[F_IN * HC];      // W1 transposed [k][c], fp16
__device__ float    g_as1[NMAX * H1];
__device__ float    g_ad1[NMAX * H1];
__device__ int      g_src[EAMAX];
__device__ int      g_dst[EAMAX];
__device__ int      g_cnt[NMAX];
__device__ int      g_rowstart[NMAX];
__device__ int      g_fill[NMAX];
__device__ int      g_csr_src[EAMAX];
__device__ int      g_bsum[64];
__device__ int      g_boff[64];
__device__ float    g_h2[NMAX * 2];
__device__ float    g_as2[NMAX];
__device__ float    g_ad2[NMAX];
__device__ int      g_is64;

// ---------------- helpers ----------------
__device__ __forceinline__ float lrelu(float x) { return x > 0.f ? x : 0.2f * x; }

__device__ __forceinline__ uint32_t h2u(__half2 h) {
    return *reinterpret_cast<uint32_t*>(&h);
}
__device__ __forceinline__ uint32_t packh2(float lo, float hi) {
    return h2u(__float22half2_rn(make_float2(lo, hi)));
}

__device__ __forceinline__ uint32_t sm2u32(const void* p) {
    return (uint32_t)__cvta_generic_to_shared(p);
}
__device__ __forceinline__ void ldsm_x4(uint32_t* r, uint32_t addr) {
    asm volatile("ldmatrix.sync.aligned.m8n8.x4.shared.b16 {%0,%1,%2,%3}, [%4];"
                 : "=r"(r[0]), "=r"(r[1]), "=r"(r[2]), "=r"(r[3]) : "r"(addr));
}
__device__ __forceinline__ void ldsm_x4_t(uint32_t* r, uint32_t addr) {
    asm volatile("ldmatrix.sync.aligned.m8n8.x4.trans.shared.b16 {%0,%1,%2,%3}, [%4];"
                 : "=r"(r[0]), "=r"(r[1]), "=r"(r[2]), "=r"(r[3]) : "r"(addr));
}
__device__ __forceinline__ void mma16816(float* d, const uint32_t* a,
                                         uint32_t b0, uint32_t b1) {
    asm volatile(
        "mma.sync.aligned.m16n8k16.row.col.f32.f16.f16.f32 "
        "{%0,%1,%2,%3}, {%4,%5,%6,%7}, {%8,%9}, {%0,%1,%2,%3};"
        : "+f"(d[0]), "+f"(d[1]), "+f"(d[2]), "+f"(d[3])
        : "r"(a[0]), "r"(a[1]), "r"(a[2]), "r"(a[3]), "r"(b0), "r"(b1));
}

// ---------------- setup kernels ----------------
__global__ void detect_kernel(const void* ei, int twoE, long long N) {
    int lane = threadIdx.x;
    const long long* p = (const long long*)ei;
    int m = twoE < 64 ? twoE : 64;
    int bad = 0;
#pragma unroll
    for (int r = 0; r < 2; r++) {
        int i = lane + 32 * r;
        if (i < m) {
            long long v = p[i];
            if (v < 0 || v >= N) bad = 1;
        }
    }
    unsigned anybad = __ballot_sync(0xFFFFFFFFu, bad);
    if (lane == 0) g_is64 = (anybad == 0u) ? 1 : 0;
}

__global__ void zerocnt_kernel(int N) {
    int i = blockIdx.x * blockDim.x + threadIdx.x;
    if (i < N) g_cnt[i] = 0;
}

// Wt transpose (fp32 -> fp16) + zero as1/ad1
__global__ void wtzero_kernel(const float* __restrict__ W1, int N) {
    int i = blockIdx.x * blockDim.x + threadIdx.x;
    if (i < F_IN * HC) {
        int k = i / HC, c = i % HC;
        g_Wth[i] = __float2half_rn(W1[c * F_IN + k]);
    }
    if (i < N * H1) { g_as1[i] = 0.f; g_ad1[i] = 0.f; }
}

// split edge_index + self loops + fused dst histogram
__global__ void edges_hist_kernel(const void* ei, int E, int N) {
    int i = blockIdx.x * blockDim.x + threadIdx.x;
    int twoE = 2 * E;
    if (i < twoE) {
        int v;
        if (g_is64) v = (int)((const long long*)ei)[i];
        else        v = ((const int*)ei)[i];
        if (i < E) g_src[i] = v;
        else {
            g_dst[i - E] = v;
            atomicAdd(&g_cnt[v], 1);
        }
    } else if (i < twoE + N) {
        int n = i - twoE;
        g_src[E + n] = n;
        g_dst[E + n] = n;
        atomicAdd(&g_cnt[n], 1);
    }
}

// hierarchical scan
__global__ void scan1_kernel(int N) {
    __shared__ int sp[SCB];
    int t = threadIdx.x;
    int i = blockIdx.x * SCB + t;
    int val = (i < N) ? g_cnt[i] : 0;
    sp[t] = val;
    __syncthreads();
    for (int off = 1; off < SCB; off <<= 1) {
        int v = (t >= off) ? sp[t - off] : 0;
        __syncthreads();
        sp[t] += v;
        __syncthreads();
    }
    if (i < N) g_rowstart[i] = sp[t] - val;
    if (t == SCB - 1) g_bsum[blockIdx.x] = sp[t];
}

__global__ void scan2_kernel(int nb) {
    __shared__ int sp[256];
    int t = threadIdx.x;
    int val = (t < nb) ? g_bsum[t] : 0;
    sp[t] = val;
    __syncthreads();
    for (int off = 1; off < 256; off <<= 1) {
        int v = (t >= off) ? sp[t - off] : 0;
        __syncthreads();
        sp[t] += v;
        __syncthreads();
    }
    if (t < nb) g_boff[t] = sp[t] - val;
}

__global__ void scan3_kernel(int N) {
    int i = blockIdx.x * blockDim.x + threadIdx.x;
    if (i < N) {
        int v = g_rowstart[i] + g_boff[i >> 10];
        g_rowstart[i] = v;
        g_fill[i]     = v;
    }
}

__global__ void scatter_kernel(int EA) {
    int e = blockIdx.x * blockDim.x + threadIdx.x;
    if (e >= EA) return;
    int d = g_dst[e];
    int pos = atomicAdd(&g_fill[d], 1);
    g_csr_src[pos] = g_src[e];
}

// ------------- h1 = x @ W1^T : fp16 HMMA (m16n8k16) + ldmatrix --------------
// 8 warps = 4(m) x 2(n); warp tile 32x64. KC=16 per chunk, 8 chunks,
// register double-buffered staging, one syncthreads per chunk.
__global__ void __launch_bounds__(256, 2) gemm1_kernel(const float* __restrict__ x, int N,
                                                       const float* __restrict__ att_src,
                                                       const float* __restrict__ att_dst) {
    __shared__ __half Asm[2][128 * AST];   // [node][k] row-major, stride 24 halves
    __shared__ __half Wsm[2][KC * WST];    // [k][c] row-major, stride 136 halves
    int t    = threadIdx.x;
    int w    = t >> 5;
    int lane = t & 31;
    int wm   = w & 3;          // rows wm*32 .. +32
    int wn   = w >> 2;         // cols wn*64 .. +64
    int n0   = blockIdx.x * BMt;
    int c0   = blockIdx.y * BNt;

    // staging assignment
    int rowA = t & 127, jA = t >> 7;                 // A: 128 rows x 2 8-half chunks
    bool aok = (n0 + rowA) < N;
    const float* xrow = &x[(size_t)(n0 + rowA) * F_IN + jA * 8];
    int kW = t >> 4, cW = (t & 15) * 8;              // W: 16 k-rows x 16 col-octets
    const __half* wsrc = &g_Wth[(size_t)kW * HC + c0 + cW];
    __half* adst0 = &Asm[0][rowA * AST + jA * 8];
    __half* adst1 = &Asm[1][rowA * AST + jA * 8];
    __half* wdst0 = &Wsm[0][kW * WST + cW];
    __half* wdst1 = &Wsm[1][kW * WST + cW];

    // ldmatrix addresses (constant per thread)
    uint32_t aaddr0 = sm2u32(&Asm[0][(wm * 32 + (lane & 15)) * AST + (lane >> 4) * 8]);
    uint32_t aaddr1 = sm2u32(&Asm[1][(wm * 32 + (lane & 15)) * AST + (lane >> 4) * 8]);
    uint32_t baddr0 = sm2u32(&Wsm[0][(lane & 15) * WST + wn * 64 + (lane >> 4) * 8]);
    uint32_t baddr1 = sm2u32(&Wsm[1][(lane & 15) * WST + wn * 64 + (lane >> 4) * 8]);

    float acc[2][8][4];
#pragma unroll
    for (int mi = 0; mi < 2; mi++)
#pragma unroll
        for (int ni = 0; ni < 8; ni++)
#pragma unroll
            for (int j = 0; j < 4; j++) acc[mi][ni][j] = 0.f;

    // prologue: stage chunk 0 -> buffer 0
    {
        float4 q0 = make_float4(0.f, 0.f, 0.f, 0.f), q1 = q0;
        if (aok) { q0 = *(const float4*)&xrow[0]; q1 = *(const float4*)&xrow[4]; }
        uint4 pa;
        pa.x = packh2(q0.x, q0.y);
        pa.y = packh2(q0.z, q0.w);
        pa.z = packh2(q1.x, q1.y);
        pa.w = packh2(q1.z, q1.w);
        *(uint4*)adst0 = pa;
        *(uint4*)wdst0 = *(const uint4*)wsrc;
        __syncthreads();
    }

    for (int it = 0; it < 8; it++) {
        int cur = it & 1;
        float4 q0 = make_float4(0.f, 0.f, 0.f, 0.f), q1 = q0;
        uint4 wv = make_uint4(0u, 0u, 0u, 0u);
        if (it < 7) {
            int k0 = (it + 1) * KC;
            if (aok) { q0 = *(const float4*)&xrow[k0]; q1 = *(const float4*)&xrow[k0 + 4]; }
            wv = *(const uint4*)(wsrc + (size_t)k0 * HC);
        }
        // fragment loads
        uint32_t a[2][4], b[4][4];
        uint32_t aa = cur ? aaddr1 : aaddr0;
        uint32_t bb = cur ? baddr1 : baddr0;
        ldsm_x4(a[0], aa);
        ldsm_x4(a[1], aa + 16 * AST * 2);
#pragma unroll
        for (int g = 0; g < 4; g++)
            ldsm_x4_t(b[g], bb + g * 16 * 2);
        // 16 HMMA
#pragma unroll
        for (int ni = 0; ni < 8; ni++) {
            uint32_t b0 = b[ni >> 1][(ni & 1) * 2 + 0];
            uint32_t b1 = b[ni >> 1][(ni & 1) * 2 + 1];
            mma16816(acc[0][ni], a[0], b0, b1);
            mma16816(acc[1][ni], a[1], b0, b1);
        }
        if (it < 7) {
            uint4 pa;
            pa.x = packh2(q0.x, q0.y);
            pa.y = packh2(q0.z, q0.w);
            pa.z = packh2(q1.x, q1.y);
            pa.w = packh2(q1.z, q1.w);
            *(uint4*)(cur ? adst0 : adst1) = pa;
            *(uint4*)(cur ? wdst0 : wdst1) = wv;
            __syncthreads();
        }
    }

    // epilogue: store h1 (fp16) + partial attention dots (one head per warp)
    int r  = lane >> 2;        // acc row group 0..7
    int kq = lane & 3;         // acc col pair 0..3
    int hbase = (c0 + wn * 64) >> 6;
    float sA[2][2] = {{0.f, 0.f}, {0.f, 0.f}};
    float dA[2][2] = {{0.f, 0.f}, {0.f, 0.f}};
#pragma unroll
    for (int mi = 0; mi < 2; mi++) {
        int row_lo = n0 + wm * 32 + mi * 16 + r;
        int row_hi = row_lo + 8;
#pragma unroll
        for (int ni = 0; ni < 8; ni++) {
            const float* dd = acc[mi][ni];
            int col = c0 + wn * 64 + ni * 8 + 2 * kq;
            if (row_lo < N) {
                uint32_t pv = packh2(dd[0], dd[1]);
                *(uint32_t*)&g_h1h[(size_t)row_lo * HC + col] = pv;
            }
            if (row_hi < N) {
                uint32_t pv = packh2(dd[2], dd[3]);
                *(uint32_t*)&g_h1h[(size_t)row_hi * HC + col] = pv;
            }
            float2 as = *(const float2*)&att_src[col];
            float2 ad = *(const float2*)&att_dst[col];
            sA[mi][0] += dd[0] * as.x + dd[1] * as.y;
            sA[mi][1] += dd[2] * as.x + dd[3] * as.y;
            dA[mi][0] += dd[0] * ad.x + dd[1] * ad.y;
            dA[mi][1] += dd[2] * ad.x + dd[3] * ad.y;
        }
    }
#pragma unroll
    for (int mi = 0; mi < 2; mi++)
#pragma unroll
        for (int j = 0; j < 2; j++) {
            sA[mi][j] += __shfl_down_sync(0xFFFFFFFFu, sA[mi][j], 2, 4);
            sA[mi][j] += __shfl_down_sync(0xFFFFFFFFu, sA[mi][j], 1, 4);
            dA[mi][j] += __shfl_down_sync(0xFFFFFFFFu, dA[mi][j], 2, 4);
            dA[mi][j] += __shfl_down_sync(0xFFFFFFFFu, dA[mi][j], 1, 4);
        }
    if (kq == 0) {
#pragma unroll
        for (int mi = 0; mi < 2; mi++)
#pragma unroll
            for (int j = 0; j < 2; j++) {
                int node = n0 + wm * 32 + mi * 16 + j * 8 + r;
                if (node < N) {
                    atomicAdd(&g_as1[node * H1 + hbase], sA[mi][j]);
                    atomicAdd(&g_ad1[node * H1 + hbase], dA[mi][j]);
                }
            }
    }
}

// ---- fused layer-1 softmax+aggregation+layer-2 projection -------------------
// One WARP per destination node; fp16 gather (16B/lane/edge), 4-edge unroll.
__global__ void agg1_kernel(const float* __restrict__ b1,
                            const float* __restrict__ W2,
                            const float* __restrict__ att_src2,
                            const float* __restrict__ att_dst2, int N) {
    int gid  = blockIdx.x * blockDim.x + threadIdx.x;
    int n    = gid >> 5;
    int lane = gid & 31;
    if (n >= N) return;
    int start = g_rowstart[n];
    int deg   = g_cnt[n];
    int cbase = lane * 8;
    int h     = lane >> 3;
    float ad  = g_ad1[n * 4 + h];

    float A[8];
#pragma unroll
    for (int j = 0; j < 8; j++) A[j] = 0.f;
    float den = 0.f;

    int e = 0;
    for (; e + 4 <= deg; e += 4) {
        int s0 = g_csr_src[start + e + 0];
        int s1 = g_csr_src[start + e + 1];
        int s2 = g_csr_src[start + e + 2];
        int s3 = g_csr_src[start + e + 3];
        float a0 = g_as1[s0 * 4 + h];
        float a1 = g_as1[s1 * 4 + h];
        float a2 = g_as1[s2 * 4 + h];
        float a3 = g_as1[s3 * 4 + h];
        uint4 v0 = *(const uint4*)&g_h1h[(size_t)s0 * HC + cbase];
        uint4 v1 = *(const uint4*)&g_h1h[(size_t)s1 * HC + cbase];
        uint4 v2 = *(const uint4*)&g_h1h[(size_t)s2 * HC + cbase];
        uint4 v3 = *(const uint4*)&g_h1h[(size_t)s3 * HC + cbase];
        float x0 = __expf(lrelu(a0 + ad));
        float x1 = __expf(lrelu(a1 + ad));
        float x2 = __expf(lrelu(a2 + ad));
        float x3 = __expf(lrelu(a3 + ad));
        den += (x0 + x1) + (x2 + x3);
        const uint32_t* vv[4] = {&v0.x, &v1.x, &v2.x, &v3.x};
        float xs[4] = {x0, x1, x2, x3};
#pragma unroll
        for (int q = 0; q < 4; q++) {
            float xq = xs[q];
#pragma unroll
            for (int j = 0; j < 4; j++) {
                float2 f = __half22float2(*(const __half2*)&vv[q][j]);
                A[2 * j + 0] += xq * f.x;
                A[2 * j + 1] += xq * f.y;
            }
        }
    }
    for (; e < deg; e++) {
        int s0 = g_csr_src[start + e];
        float a0 = g_as1[s0 * 4 + h];
        uint4 v0 = *(const uint4*)&g_h1h[(size_t)s0 * HC + cbase];
        float x0 = __expf(lrelu(a0 + ad));
        den += x0;
        const uint32_t* vv = &v0.x;
#pragma unroll
        for (int j = 0; j < 4; j++) {
            float2 f = __half22float2(*(const __half2*)&vv[j]);
            A[2 * j + 0] += x0 * f.x;
            A[2 * j + 1] += x0 * f.y;
        }
    }

    float inv = 1.f / (den + 1e-16f);
    const float4* b4 = (const float4*)&b1[cbase];
    float4 bb0 = b4[0], bb1 = b4[1];
    float y[8];
    y[0] = fmaxf(A[0] * inv + bb0.x, 0.f);
    y[1] = fmaxf(A[1] * inv + bb0.y, 0.f);
    y[2] = fmaxf(A[2] * inv + bb0.z, 0.f);
    y[3] = fmaxf(A[3] * inv + bb0.w, 0.f);
    y[4] = fmaxf(A[4] * inv + bb1.x, 0.f);
    y[5] = fmaxf(A[5] * inv + bb1.y, 0.f);
    y[6] = fmaxf(A[6] * inv + bb1.z, 0.f);
    y[7] = fmaxf(A[7] * inv + bb1.w, 0.f);

    const float4* w0q = (const float4*)&W2[cbase];
    const float4* w1q = (const float4*)&W2[HC + cbase];
    float4 wa0 = w0q[0], wa1 = w0q[1];
    float4 wb0 = w1q[0], wb1 = w1q[1];
    float p0 = y[0] * wa0.x + y[1] * wa0.y + y[2] * wa0.z + y[3] * wa0.w
             + y[4] * wa1.x + y[5] * wa1.y + y[6] * wa1.z + y[7] * wa1.w;
    float p1 = y[0] * wb0.x + y[1] * wb0.y + y[2] * wb0.z + y[3] * wb0.w
             + y[4] * wb1.x + y[5] * wb1.y + y[6] * wb1.z + y[7] * wb1.w;
#pragma unroll
    for (int o = 16; o; o >>= 1) {
        p0 += __shfl_down_sync(0xFFFFFFFFu, p0, o);
        p1 += __shfl_down_sync(0xFFFFFFFFu, p1, o);
    }
    if (lane == 0) {
        g_h2[n * 2 + 0] = p0;
        g_h2[n * 2 + 1] = p1;
        g_as2[n] = p0 * att_src2[0] + p1 * att_src2[1];
        g_ad2[n] = p0 * att_dst2[0] + p1 * att_dst2[1];
    }
}

// ---------------- fused layer-2: one warp per destination node --------------
__global__ void agg2_kernel(const float* __restrict__ b2,
                            float* __restrict__ out, int N) {
    int gid  = blockIdx.x * blockDim.x + threadIdx.x;
    int n    = gid >> 5;
    int lane = gid & 31;
    if (n >= N) return;
    int start = g_rowstart[n];
    int deg   = g_cnt[n];
    float adv = g_ad2[n];

    float den = 0.f, a0 = 0.f, a1 = 0.f;
    for (int e = lane; e < deg; e += 32) {
        int s  = g_csr_src[start + e];
        float ex = __expf(lrelu(g_as2[s] + adv));
        den += ex;
        float2 hv = *(const float2*)&g_h2[s * 2];
        a0 += ex * hv.x;
        a1 += ex * hv.y;
    }
#pragma unroll
    for (int o = 16; o; o >>= 1) {
        den += __shfl_xor_sync(0xFFFFFFFFu, den, o);
        a0  += __shfl_xor_sync(0xFFFFFFFFu, a0, o);
        a1  += __shfl_xor_sync(0xFFFFFFFFu, a1, o);
    }
    if (lane == 0) {
        float inv = 1.f / (den + 1e-16f);
        out[n * 2 + 0] = a0 * inv + b2[0];
        out[n * 2 + 1] = a1 * inv + b2[1];
    }
}

// ---------------- launch ----------------
extern "C" void kernel_launch(void* const* d_in, const int* in_sizes, int n_in,
                              void* d_out, int out_size) {
    const float* x        = (const float*)d_in[0];
    const void*  ei       = d_in[1];
    const float* W1       = (const float*)d_in[2];
    const float* att_src1 = (const float*)d_in[3];
    const float* att_dst1 = (const float*)d_in[4];
    const float* b1       = (const float*)d_in[5];
    const float* W2       = (const float*)d_in[6];
    const float* att_src2 = (const float*)d_in[7];
    const float* att_dst2 = (const float*)d_in[8];
    const float* b2       = (const float*)d_in[9];

    int N  = in_sizes[0] / F_IN;
    int E  = in_sizes[1] / 2;
    int EA = E + N;

    const int B = 256;
    int gE = (EA + B - 1) / B;
    int nb = (N + SCB - 1) / SCB;

    // Side stream + events for forked capture (created once, host-side only).
    static cudaStream_t sB = 0;
    static cudaEvent_t  ev0 = 0, evB = 0;
    if (!sB) {
        cudaStreamCreateWithFlags(&sB, cudaStreamNonBlocking);
        cudaEventCreateWithFlags(&ev0, cudaEventDisableTiming);
        cudaEventCreateWithFlags(&evB, cudaEventDisableTiming);
    }

    // -------- main stream (0): edge-side prologue --------
    detect_kernel<<<1, 32>>>(ei, 2 * E, (long long)N);                     // [0]
    zerocnt_kernel<<<(N + B - 1) / B, B>>>(N);                             // [1]

    // -------- fork: branch A (wt + gemm) on sB --------
    cudaEventRecord(ev0, 0);
    cudaStreamWaitEvent(sB, ev0, 0);
    wtzero_kernel<<<(N * H1 + B - 1) / B, B, 0, sB>>>(W1, N);              // [2]
    dim3 gg((N + BMt - 1) / BMt, HC / BNt);
    gemm1_kernel<<<gg, 256, 0, sB>>>(x, N, att_src1, att_dst1);            // [3] (profiled)
    cudaEventRecord(evB, sB);

    // -------- branch B: CSR build on stream 0 (overlaps gemm) --------
    edges_hist_kernel<<<(2 * E + N + B - 1) / B, B>>>(ei, E, N);           // [4]
    scan1_kernel<<<nb, SCB>>>(N);                                          // [5]
    scan2_kernel<<<1, 256>>>(nb);                                          // [6]
    scan3_kernel<<<(N + B - 1) / B, B>>>(N);                               // [7]
    scatter_kernel<<<gE, B>>>(EA);                                         // [8]

    // -------- join + aggregation --------
    cudaStreamWaitEvent(0, evB, 0);
    agg1_kernel<<<(N * 32 + B - 1) / B, B>>>(b1, W2, att_src2, att_dst2, N); // [9]
    agg2_kernel<<<(N * 32 + B - 1) / B, B>>>(b2, (float*)d_out, N);          // [10]
}